// round 11
// baseline (speedup 1.0000x reference)
#include <cuda_runtime.h>
#include <cuda_bf16.h>
#include <cstdint>

#define B_  2
#define S_  2048
#define H_  2048
#define NH  16
#define HD  128
#define M_  (B_*S_)
#define NQ  (S_/128)

extern __shared__ __align__(16) unsigned char sm_raw[];

// ---------------------------------------------------------------------------
// Scratch
// ---------------------------------------------------------------------------
__device__ __nv_bfloat16 g_xhi[(size_t)M_*H_];
__device__ __nv_bfloat16 g_xlo[(size_t)M_*H_];
__device__ __nv_bfloat16 g_whi[4][(size_t)H_*H_];
__device__ __nv_bfloat16 g_wlo[4][(size_t)H_*H_];
__device__ __nv_bfloat16 g_qhi[(size_t)M_*H_];
__device__ __nv_bfloat16 g_qlo[(size_t)M_*H_];
__device__ __nv_bfloat16 g_khi[(size_t)M_*H_];
__device__ __nv_bfloat16 g_klo[(size_t)M_*H_];
__device__ __nv_bfloat16 g_vhi[(size_t)M_*H_];
__device__ __nv_bfloat16 g_vlo[(size_t)M_*H_];
__device__ __nv_bfloat16 g_chi[(size_t)M_*H_];
__device__ __nv_bfloat16 g_clo[(size_t)M_*H_];

// ---------------------------------------------------------------------------
__device__ __forceinline__ void split1(float v, __nv_bfloat16& h, __nv_bfloat16& l) {
    h = __float2bfloat16(v);
    l = __float2bfloat16(v - __bfloat162float(h));
}

__global__ void split_bf16(const float* __restrict__ in,
                           __nv_bfloat16* __restrict__ hi,
                           __nv_bfloat16* __restrict__ lo, int n4)
{
    int i = blockIdx.x * blockDim.x + threadIdx.x;
    int stride = gridDim.x * blockDim.x;
    for (; i < n4; i += stride) {
        float4 v = ((const float4*)in)[i];
        __nv_bfloat16 h0,h1,h2,h3,l0,l1,l2,l3;
        split1(v.x,h0,l0); split1(v.y,h1,l1); split1(v.z,h2,l2); split1(v.w,h3,l3);
        ((__nv_bfloat162*)hi)[2*i+0] = __nv_bfloat162(h0,h1);
        ((__nv_bfloat162*)hi)[2*i+1] = __nv_bfloat162(h2,h3);
        ((__nv_bfloat162*)lo)[2*i+0] = __nv_bfloat162(l0,l1);
        ((__nv_bfloat162*)lo)[2*i+1] = __nv_bfloat162(l2,l3);
    }
}

__global__ void split_bf16_w4(const float* __restrict__ w0, const float* __restrict__ w1,
                              const float* __restrict__ w2, const float* __restrict__ w3,
                              __nv_bfloat16* __restrict__ hi, __nv_bfloat16* __restrict__ lo,
                              int n4)
{
    const float* src[4] = {w0, w1, w2, w3};
    const float* in = src[blockIdx.y];
    __nv_bfloat16* hw = hi + (size_t)blockIdx.y * H_ * H_;
    __nv_bfloat16* lw = lo + (size_t)blockIdx.y * H_ * H_;
    int i = blockIdx.x * blockDim.x + threadIdx.x;
    int stride = gridDim.x * blockDim.x;
    for (; i < n4; i += stride) {
        float4 v = ((const float4*)in)[i];
        __nv_bfloat16 h0,h1,h2,h3,l0,l1,l2,l3;
        split1(v.x,h0,l0); split1(v.y,h1,l1); split1(v.z,h2,l2); split1(v.w,h3,l3);
        ((__nv_bfloat162*)hw)[2*i+0] = __nv_bfloat162(h0,h1);
        ((__nv_bfloat162*)hw)[2*i+1] = __nv_bfloat162(h2,h3);
        ((__nv_bfloat162*)lw)[2*i+0] = __nv_bfloat162(l0,l1);
        ((__nv_bfloat162*)lw)[2*i+1] = __nv_bfloat162(l2,l3);
    }
}

// ---------------------------------------------------------------------------
// PTX helpers
// ---------------------------------------------------------------------------
__device__ __forceinline__ uint32_t smem_u32(const void* p) {
    uint32_t a;
    asm("{ .reg .u64 t; cvta.to.shared.u64 t, %1; cvt.u32.u64 %0, t; }" : "=r"(a) : "l"(p));
    return a;
}
__device__ __forceinline__ void cp16(uint32_t s, const void* g) {
    asm volatile("cp.async.cg.shared.global [%0], [%1], 16;\n" :: "r"(s), "l"(g));
}
__device__ __forceinline__ void cp_commit() { asm volatile("cp.async.commit_group;\n"); }
template<int N> __device__ __forceinline__ void cp_wait() {
    asm volatile("cp.async.wait_group %0;\n" :: "n"(N));
}
__device__ __forceinline__ void mma16816(float* d, const uint32_t* a, const uint32_t* b) {
    asm volatile("mma.sync.aligned.m16n8k16.row.col.f32.bf16.bf16.f32 "
                 "{%0,%1,%2,%3}, {%4,%5,%6,%7}, {%8,%9}, {%0,%1,%2,%3};\n"
                 : "+f"(d[0]), "+f"(d[1]), "+f"(d[2]), "+f"(d[3])
                 : "r"(a[0]), "r"(a[1]), "r"(a[2]), "r"(a[3]), "r"(b[0]), "r"(b[1]));
}
__device__ __forceinline__ void ldsm4(uint32_t* r, uint32_t a) {
    asm volatile("ldmatrix.sync.aligned.m8n8.x4.shared.b16 {%0,%1,%2,%3}, [%4];"
                 : "=r"(r[0]), "=r"(r[1]), "=r"(r[2]), "=r"(r[3]) : "r"(a));
}
__device__ __forceinline__ void ldsm4t(uint32_t* r, uint32_t a) {
    asm volatile("ldmatrix.sync.aligned.m8n8.x4.trans.shared.b16 {%0,%1,%2,%3}, [%4];"
                 : "=r"(r[0]), "=r"(r[1]), "=r"(r[2]), "=r"(r[3]) : "r"(a));
}
__device__ __forceinline__ uint32_t packbf(float a, float b) {
    __nv_bfloat162 h(__float2bfloat16(a), __float2bfloat16(b));
    return *(uint32_t*)&h;
}

// ---------------------------------------------------------------------------
// bf16x3 GEMM (NT): C = A * W^T + bias, mma.sync + ldmatrix.
// CTA tile 128(M) x 256(N), BK=32, 8 warps (2x4), warp tile 64x64.
// MODE 0: QKV fused via blockIdx.z, hi/lo out scattered [b,head,s,d] (*scale Q).
// MODE 1: fp32 out [M,N].
// smem per stage (bytes): Ahi 10240, Alo 10240, Bhi 20480, Blo 20480 = 61440.
// ---------------------------------------------------------------------------
#define GSTRIDE 40
#define GA_BYTES 10240
#define GB_BYTES 20480
#define GSTAGE_BYTES 61440
#define GEMM_SMEM_BYTES (2*GSTAGE_BYTES)

template<int MODE>
__global__ __launch_bounds__(256) void gemm_bf16x3(
    const __nv_bfloat16* __restrict__ Ahi, const __nv_bfloat16* __restrict__ Alo,
    const __nv_bfloat16* __restrict__ Wh_base, const __nv_bfloat16* __restrict__ Wl_base,
    const float* __restrict__ bias0, const float* __restrict__ bias1,
    const float* __restrict__ bias2, float scale0,
    float* __restrict__ outf,
    __nv_bfloat16* __restrict__ oh0, __nv_bfloat16* __restrict__ ol0,
    __nv_bfloat16* __restrict__ oh1, __nv_bfloat16* __restrict__ ol1,
    __nv_bfloat16* __restrict__ oh2, __nv_bfloat16* __restrict__ ol2)
{
    const int K = H_;
    const int tid  = threadIdx.x;
    const int lane = tid & 31, warp = tid >> 5;
    const int g = lane >> 2, tg = lane & 3;
    const int wm = (warp >> 2) * 64, wn = (warp & 3) * 64;
    const int bm = blockIdx.y * 128, bn = blockIdx.x * 256;
    const int z = (MODE == 0) ? blockIdx.z : 0;

    const __nv_bfloat16* Whi = Wh_base + (size_t)z * H_ * H_;
    const __nv_bfloat16* Wlo = Wl_base + (size_t)z * H_ * H_;
    const float* bias = (z == 0) ? bias0 : (z == 1) ? bias1 : bias2;
    const float scale = (MODE == 0 && z == 0) ? scale0 : 1.f;
    __nv_bfloat16* outhi = (z == 0) ? oh0 : (z == 1) ? oh1 : oh2;
    __nv_bfloat16* outlo = (z == 0) ? ol0 : (z == 1) ? ol1 : ol2;

    const uint32_t sbase = smem_u32(sm_raw);

    auto issue = [&](int kt, int buf) {
        const int k0 = kt * 32;
        const uint32_t sb = sbase + buf * GSTAGE_BYTES;
        // A: 1024 x 16B chunks (hi 512, lo 512); rows 128, 4 chunks/row
        #pragma unroll
        for (int i = 0; i < 4; i++) {
            const int ch = tid + i * 256;
            const int part = ch >> 9;
            const int c2 = ch & 511;
            const int r = c2 >> 2, c16 = c2 & 3;
            const uint32_t dst = sb + part * GA_BYTES + (uint32_t)(r * GSTRIDE + c16 * 8) * 2;
            const __nv_bfloat16* src = (part ? Alo : Ahi) + (size_t)(bm + r) * K + k0 + c16 * 8;
            cp16(dst, src);
        }
        // B: 2048 x 16B chunks (hi 1024, lo 1024); rows 256, 4 chunks/row
        #pragma unroll
        for (int i = 0; i < 8; i++) {
            const int ch = tid + i * 256;
            const int part = ch >> 10;
            const int c2 = ch & 1023;
            const int r = c2 >> 2, c16 = c2 & 3;
            const uint32_t dst = sb + 2 * GA_BYTES + part * GB_BYTES
                               + (uint32_t)(r * GSTRIDE + c16 * 8) * 2;
            const __nv_bfloat16* src = (part ? Wlo : Whi) + (size_t)(bn + r) * K + k0 + c16 * 8;
            cp16(dst, src);
        }
        cp_commit();
    };

    float acc[4][8][4] = {};
    issue(0, 0);
    issue(1, 1);

    const int sub = lane & 7;
    const uint32_t a_off = ((uint32_t)((8 * ((lane >> 3) & 1) + sub) * GSTRIDE
                                       + (lane >> 4) * 8)) * 2;
    const uint32_t b_off = ((uint32_t)((8 * (lane >> 4) + sub) * GSTRIDE
                                       + ((lane >> 3) & 1) * 8)) * 2;

    const int NT = K / 32;
    for (int kt = 0; kt < NT; kt++) {
        if (kt < NT - 1) cp_wait<1>(); else cp_wait<0>();
        __syncthreads();

        const uint32_t stb = sbase + (kt & 1) * GSTAGE_BYTES;

        #pragma unroll
        for (int kh = 0; kh < 32; kh += 16) {
            const uint32_t Aaddr = stb + a_off + (uint32_t)(wm * GSTRIDE + kh) * 2;
            const uint32_t Baddr = stb + 2 * GA_BYTES + b_off
                                 + (uint32_t)(wn * GSTRIDE + kh) * 2;
            uint32_t afh[4][4], afl[4][4], bh[4][4], bl[4][4];
            #pragma unroll
            for (int mi = 0; mi < 4; mi++)
                ldsm4(afh[mi], Aaddr + (uint32_t)(mi * 16 * GSTRIDE) * 2);
            #pragma unroll
            for (int n2 = 0; n2 < 4; n2++)
                ldsm4(bh[n2], Baddr + (uint32_t)(n2 * 16 * GSTRIDE) * 2);
            // hi*hi
            #pragma unroll
            for (int mi = 0; mi < 4; mi++)
                #pragma unroll
                for (int ni = 0; ni < 8; ni++)
                    mma16816(acc[mi][ni], afh[mi], bh[ni >> 1] + (ni & 1) * 2);
            // hi * B-lo
            #pragma unroll
            for (int n2 = 0; n2 < 4; n2++)
                ldsm4(bl[n2], Baddr + GB_BYTES + (uint32_t)(n2 * 16 * GSTRIDE) * 2);
            #pragma unroll
            for (int mi = 0; mi < 4; mi++)
                #pragma unroll
                for (int ni = 0; ni < 8; ni++)
                    mma16816(acc[mi][ni], afh[mi], bl[ni >> 1] + (ni & 1) * 2);
            // A-lo * hi
            #pragma unroll
            for (int mi = 0; mi < 4; mi++)
                ldsm4(afl[mi], Aaddr + GA_BYTES + (uint32_t)(mi * 16 * GSTRIDE) * 2);
            #pragma unroll
            for (int mi = 0; mi < 4; mi++)
                #pragma unroll
                for (int ni = 0; ni < 8; ni++)
                    mma16816(acc[mi][ni], afl[mi], bh[ni >> 1] + (ni & 1) * 2);
        }
        __syncthreads();
        if (kt + 2 < NT) issue(kt + 2, kt & 1);
    }

    // epilogue
    #pragma unroll
    for (int ni = 0; ni < 8; ni++) {
        const int n0 = bn + wn + ni * 8 + 2 * tg;
        const float b0 = bias[n0], b1 = bias[n0 + 1];
        #pragma unroll
        for (int mi = 0; mi < 4; mi++) {
            #pragma unroll
            for (int h = 0; h < 2; h++) {
                const int row = bm + wm + mi * 16 + g + h * 8;
                float vx = acc[mi][ni][2*h+0] + b0;
                float vy = acc[mi][ni][2*h+1] + b1;
                if (MODE == 1) {
                    *(float2*)(outf + (size_t)row * H_ + n0) = make_float2(vx, vy);
                } else {
                    vx *= scale; vy *= scale;
                    __nv_bfloat16 hx, hy, lx, ly;
                    split1(vx, hx, lx); split1(vy, hy, ly);
                    const int b  = row >> 11;
                    const int s  = row & 2047;
                    const int hd = n0 >> 7;
                    const int dd = n0 & 127;
                    size_t idx = ((size_t)(b * NH + hd) * S_ + s) * HD + dd;
                    *(__nv_bfloat162*)(outhi + idx) = __nv_bfloat162(hx, hy);
                    *(__nv_bfloat162*)(outlo + idx) = __nv_bfloat162(lx, ly);
                }
            }
        }
    }
}

// ---------------------------------------------------------------------------
// Flash attention v3b (unchanged from R10)
// ---------------------------------------------------------------------------
#define FV_K(st) ((st)*17408)
#define FV_V(st) (34816 + (st)*17408)
#define FV_SMEM_BYTES (69632*2)

__global__ __launch_bounds__(256) void flash_attn_v3(
    const __nv_bfloat16* __restrict__ Qhi, const __nv_bfloat16* __restrict__ Qlo,
    const __nv_bfloat16* __restrict__ Khi, const __nv_bfloat16* __restrict__ Klo,
    const __nv_bfloat16* __restrict__ Vhi, const __nv_bfloat16* __restrict__ Vlo,
    __nv_bfloat16* __restrict__ Chi, __nv_bfloat16* __restrict__ Clo)
{
    __nv_bfloat16* sm = (__nv_bfloat16*)sm_raw;
    const int tid = threadIdx.x, lane = tid & 31, w = tid >> 5;
    const int g = lane >> 2, tg = lane & 3;
    const int bh = blockIdx.y, b = bh >> 4, head = bh & 15;
    const int q0 = (NQ - 1 - (int)blockIdx.x) * 128;
    const size_t base = (size_t)bh * S_ * HD;
    const uint32_t sb = smem_u32(sm);
    const int nt = q0 / 64 + 2;

    const int sub   = lane & 7;
    const int halfb = (lane >> 3) & 1;
    const int grpb  = lane >> 4;

    auto issueKV = [&](int kt, int st) {
        const int k0 = kt * 64;
        const uint32_t kb = sb + FV_K(st) * 2;
        const uint32_t vb = sb + FV_V(st) * 2;
        #pragma unroll
        for (int p = 0; p < 4; p++) {
            const int ch = tid + p * 256;
            const int r = ch >> 4, c8 = (ch & 15) * 8;
            const uint32_t off = (uint32_t)(r * 136 + c8) * 2;
            const size_t go = base + (size_t)(k0 + r) * HD + c8;
            cp16(kb + off,          Khi + go);
            cp16(kb + 17408 + off,  Klo + go);
            cp16(vb + off,          Vhi + go);
            cp16(vb + 17408 + off,  Vlo + go);
        }
        cp_commit();
    };

    issueKV(0, 0);

    uint32_t qh[8][4], ql[8][4];
    {
        const size_t r0g = base + (size_t)(q0 + w * 16 + g) * HD;
        #pragma unroll
        for (int kk = 0; kk < 8; kk++) {
            const int c = kk * 16 + 2 * tg;
            qh[kk][0] = *(const uint32_t*)(Qhi + r0g + c);
            qh[kk][1] = *(const uint32_t*)(Qhi + r0g + 8 * HD + c);
            qh[kk][2] = *(const uint32_t*)(Qhi + r0g + c + 8);
            qh[kk][3] = *(const uint32_t*)(Qhi + r0g + 8 * HD + c + 8);
            ql[kk][0] = *(const uint32_t*)(Qlo + r0g + c);
            ql[kk][1] = *(const uint32_t*)(Qlo + r0g + 8 * HD + c);
            ql[kk][2] = *(const uint32_t*)(Qlo + r0g + c + 8);
            ql[kk][3] = *(const uint32_t*)(Qlo + r0g + 8 * HD + c + 8);
        }
    }

    float oacc[16][4] = {};
    float m0 = -1e30f, m1 = -1e30f, l0 = 0.f, l1 = 0.f;
    const int r0 = q0 + w * 16 + g;

    const uint32_t kfragoff = (uint32_t)((8 * grpb + sub) * 136 + halfb * 8) * 2;
    const uint32_t vfragoff = (uint32_t)((8 * halfb + sub) * 136 + 8 * grpb) * 2;

    for (int kt = 0; kt < nt; kt++) {
        const int st = kt & 1;
        __syncthreads();
        if (kt + 1 < nt) { issueKV(kt + 1, st ^ 1); cp_wait<1>(); }
        else             { cp_wait<0>(); }
        __syncthreads();

        float sacc[8][4];
        #pragma unroll
        for (int j = 0; j < 8; j++)
            sacc[j][0] = sacc[j][1] = sacc[j][2] = sacc[j][3] = 0.f;
        const uint32_t kbase = sb + FV_K(st) * 2 + kfragoff;
        #pragma unroll
        for (int kk = 0; kk < 8; kk++) {
            #pragma unroll
            for (int jp = 0; jp < 4; jp++) {
                uint32_t bh4[4], bl4[4];
                const uint32_t ka = kbase + (uint32_t)(16 * jp * 136 + kk * 16) * 2;
                ldsm4(bh4, ka);
                ldsm4(bl4, ka + 17408);
                mma16816(sacc[2*jp],   qh[kk], bh4);
                mma16816(sacc[2*jp+1], qh[kk], bh4 + 2);
                mma16816(sacc[2*jp],   qh[kk], bl4);
                mma16816(sacc[2*jp+1], qh[kk], bl4 + 2);
                mma16816(sacc[2*jp],   ql[kk], bh4);
                mma16816(sacc[2*jp+1], ql[kk], bh4 + 2);
            }
        }

        const int k0 = kt * 64;
        if (k0 + 63 > r0) {
            #pragma unroll
            for (int j = 0; j < 8; j++) {
                const int c = k0 + j * 8 + 2 * tg;
                if (c     > r0)     sacc[j][0] = -1e30f;
                if (c + 1 > r0)     sacc[j][1] = -1e30f;
                if (c     > r0 + 8) sacc[j][2] = -1e30f;
                if (c + 1 > r0 + 8) sacc[j][3] = -1e30f;
            }
        }

        float rx0 = -1e30f, rx1 = -1e30f;
        #pragma unroll
        for (int j = 0; j < 8; j++) {
            rx0 = fmaxf(rx0, fmaxf(sacc[j][0], sacc[j][1]));
            rx1 = fmaxf(rx1, fmaxf(sacc[j][2], sacc[j][3]));
        }
        rx0 = fmaxf(rx0, __shfl_xor_sync(0xffffffffu, rx0, 1));
        rx0 = fmaxf(rx0, __shfl_xor_sync(0xffffffffu, rx0, 2));
        rx1 = fmaxf(rx1, __shfl_xor_sync(0xffffffffu, rx1, 1));
        rx1 = fmaxf(rx1, __shfl_xor_sync(0xffffffffu, rx1, 2));
        const float mn0 = fmaxf(m0, rx0), mn1 = fmaxf(m1, rx1);
        const float c0 = __expf(m0 - mn0), c1 = __expf(m1 - mn1);

        uint32_t ph0[8], ph1[8], pl0[8], pl1[8];
        float sum0 = 0.f, sum1 = 0.f;
        #pragma unroll
        for (int j = 0; j < 8; j++) {
            float p00 = __expf(sacc[j][0] - mn0);
            float p01 = __expf(sacc[j][1] - mn0);
            float p10 = __expf(sacc[j][2] - mn1);
            float p11 = __expf(sacc[j][3] - mn1);
            sum0 += p00 + p01;  sum1 += p10 + p11;
            ph0[j] = packbf(p00, p01);
            ph1[j] = packbf(p10, p11);
            __nv_bfloat162 hA = *(__nv_bfloat162*)&ph0[j];
            __nv_bfloat162 hB = *(__nv_bfloat162*)&ph1[j];
            pl0[j] = packbf(p00 - __bfloat162float(hA.x), p01 - __bfloat162float(hA.y));
            pl1[j] = packbf(p10 - __bfloat162float(hB.x), p11 - __bfloat162float(hB.y));
        }
        sum0 += __shfl_xor_sync(0xffffffffu, sum0, 1);
        sum0 += __shfl_xor_sync(0xffffffffu, sum0, 2);
        sum1 += __shfl_xor_sync(0xffffffffu, sum1, 1);
        sum1 += __shfl_xor_sync(0xffffffffu, sum1, 2);
        l0 = l0 * c0 + sum0;  m0 = mn0;
        l1 = l1 * c1 + sum1;  m1 = mn1;
        #pragma unroll
        for (int jd = 0; jd < 16; jd++) {
            oacc[jd][0] *= c0; oacc[jd][1] *= c0;
            oacc[jd][2] *= c1; oacc[jd][3] *= c1;
        }

        const uint32_t vbase = sb + FV_V(st) * 2 + vfragoff;
        #pragma unroll
        for (int kk2 = 0; kk2 < 4; kk2++) {
            uint32_t a_h[4] = { ph0[2*kk2], ph1[2*kk2], ph0[2*kk2+1], ph1[2*kk2+1] };
            uint32_t a_l[4] = { pl0[2*kk2], pl1[2*kk2], pl0[2*kk2+1], pl1[2*kk2+1] };
            #pragma unroll
            for (int jdp = 0; jdp < 8; jdp++) {
                uint32_t vh4[4], vl4[4];
                const uint32_t va = vbase + (uint32_t)(16 * kk2 * 136 + 16 * jdp) * 2;
                ldsm4t(vh4, va);
                ldsm4t(vl4, va + 17408);
                mma16816(oacc[2*jdp],   a_h, vh4);
                mma16816(oacc[2*jdp+1], a_h, vh4 + 2);
                mma16816(oacc[2*jdp],   a_l, vh4);
                mma16816(oacc[2*jdp+1], a_l, vh4 + 2);
                mma16816(oacc[2*jdp],   a_h, vl4);
                mma16816(oacc[2*jdp+1], a_h, vl4 + 2);
            }
        }
    }

    const float i0 = 1.f / l0, i1 = 1.f / l1;
    #pragma unroll
    for (int jd = 0; jd < 16; jd++) {
        const int d = jd * 8 + 2 * tg;
        const float o00 = oacc[jd][0] * i0, o01 = oacc[jd][1] * i0;
        const float o10 = oacc[jd][2] * i1, o11 = oacc[jd][3] * i1;
        const size_t idx0 = ((size_t)b * S_ + r0)     * H_ + head * HD + d;
        const size_t idx1 = ((size_t)b * S_ + r0 + 8) * H_ + head * HD + d;
        __nv_bfloat16 hx, hy, lx, ly;
        split1(o00, hx, lx); split1(o01, hy, ly);
        *(__nv_bfloat162*)(Chi + idx0) = __nv_bfloat162(hx, hy);
        *(__nv_bfloat162*)(Clo + idx0) = __nv_bfloat162(lx, ly);
        split1(o10, hx, lx); split1(o11, hy, ly);
        *(__nv_bfloat162*)(Chi + idx1) = __nv_bfloat162(hx, hy);
        *(__nv_bfloat162*)(Clo + idx1) = __nv_bfloat162(lx, ly);
    }
}

// ---------------------------------------------------------------------------
extern "C" void kernel_launch(void* const* d_in, const int* in_sizes, int n_in,
                              void* d_out, int out_size)
{
    const float* x  = (const float*)d_in[0];
    const float* wq = (const float*)d_in[1];
    const float* bq = (const float*)d_in[2];
    const float* wk = (const float*)d_in[3];
    const float* bk = (const float*)d_in[4];
    const float* wv = (const float*)d_in[5];
    const float* bv = (const float*)d_in[6];
    const float* wo = (const float*)d_in[7];
    const float* bo = (const float*)d_in[8];
    float* out = (float*)d_out;

    __nv_bfloat16 *xhi, *xlo, *whi, *wlo;
    __nv_bfloat16 *qhi, *qlo, *khi, *klo, *vhi, *vlo, *chi, *clo;
    cudaGetSymbolAddress((void**)&xhi, g_xhi);
    cudaGetSymbolAddress((void**)&xlo, g_xlo);
    cudaGetSymbolAddress((void**)&whi, g_whi);
    cudaGetSymbolAddress((void**)&wlo, g_wlo);
    cudaGetSymbolAddress((void**)&qhi, g_qhi);
    cudaGetSymbolAddress((void**)&qlo, g_qlo);
    cudaGetSymbolAddress((void**)&khi, g_khi);
    cudaGetSymbolAddress((void**)&klo, g_klo);
    cudaGetSymbolAddress((void**)&vhi, g_vhi);
    cudaGetSymbolAddress((void**)&vlo, g_vlo);
    cudaGetSymbolAddress((void**)&chi, g_chi);
    cudaGetSymbolAddress((void**)&clo, g_clo);

    static bool attr_set = false;
    if (!attr_set) {
        cudaFuncSetAttribute(gemm_bf16x3<0>, cudaFuncAttributeMaxDynamicSharedMemorySize, GEMM_SMEM_BYTES);
        cudaFuncSetAttribute(gemm_bf16x3<1>, cudaFuncAttributeMaxDynamicSharedMemorySize, GEMM_SMEM_BYTES);
        cudaFuncSetAttribute(flash_attn_v3, cudaFuncAttributeMaxDynamicSharedMemorySize, FV_SMEM_BYTES);
        attr_set = true;
    }

    const float qscale = 0.08838834764831845f;   // 1/sqrt(128)

    split_bf16<<<1024, 256>>>(x, xhi, xlo, M_*H_/4);
    split_bf16_w4<<<dim3(256, 4), 256>>>(wq, wk, wv, wo, whi, wlo, H_*H_/4);

    // Fused QKV projection
    dim3 gqkv(H_/256, M_/128, 3);   // (8, 32, 3)
    gemm_bf16x3<0><<<gqkv, 256, GEMM_SMEM_BYTES>>>(
        xhi, xlo, whi, wlo, bq, bk, bv, qscale, nullptr,
        qhi, qlo, khi, klo, vhi, vlo);

    dim3 gf(NQ, B_*NH);   // (16, 32)
    flash_attn_v3<<<gf, 256, FV_SMEM_BYTES>>>(qhi, qlo, khi, klo, vhi, vlo, chi, clo);

    // Output projection (weight slot 3)
    dim3 gg(H_/256, M_/128);        // (8, 32)
    gemm_bf16x3<1><<<gg, 256, GEMM_SMEM_BYTES>>>(
        chi, clo, whi + 3*(size_t)H_*H_, wlo + 3*(size_t)H_*H_,
        bo, bo, bo, 1.f, out,
        nullptr, nullptr, nullptr, nullptr, nullptr, nullptr);
}

// round 13
// speedup vs baseline: 1.1525x; 1.1525x over previous
#include <cuda_runtime.h>
#include <cuda_bf16.h>
#include <cuda_fp16.h>
#include <cstdint>

#define B_  2
#define S_  2048
#define H_  2048
#define NH  16
#define HD  128
#define M_  (B_*S_)
#define NQ  (S_/128)

extern __shared__ __align__(16) unsigned char sm_raw[];

// ---------------------------------------------------------------------------
// Scratch
// ---------------------------------------------------------------------------
__device__ __nv_bfloat16 g_xhi[(size_t)M_*H_];
__device__ __nv_bfloat16 g_xlo[(size_t)M_*H_];
__device__ __nv_bfloat16 g_whi[4][(size_t)H_*H_];
__device__ __nv_bfloat16 g_wlo[4][(size_t)H_*H_];
__device__ __nv_bfloat16 g_qhi[(size_t)M_*H_];   // [b,h,s,d], pre-scaled
__device__ __nv_bfloat16 g_qlo[(size_t)M_*H_];
__device__ __nv_bfloat16 g_khi[(size_t)M_*H_];   // [b,h,s,d]
__device__ __nv_bfloat16 g_klo[(size_t)M_*H_];
__device__ __half        g_vhi[(size_t)M_*H_];   // [b,h,s,d]  (fp16)
__device__ __half        g_vlo[(size_t)M_*H_];
__device__ __nv_bfloat16 g_chi[(size_t)M_*H_];   // [b,s,h]
__device__ __nv_bfloat16 g_clo[(size_t)M_*H_];

// ---------------------------------------------------------------------------
__device__ __forceinline__ void split1(float v, __nv_bfloat16& h, __nv_bfloat16& l) {
    h = __float2bfloat16(v);
    l = __float2bfloat16(v - __bfloat162float(h));
}
__device__ __forceinline__ void split1h(float v, __half& h, __half& l) {
    h = __float2half_rn(v);
    l = __float2half_rn(v - __half2float(h));
}

// Fused splitter: blockIdx.y = 0 -> x (n4x elements), 1..4 -> weights (n4w each)
__global__ void split_all(const float* __restrict__ x,
                          const float* __restrict__ w0, const float* __restrict__ w1,
                          const float* __restrict__ w2, const float* __restrict__ w3,
                          __nv_bfloat16* __restrict__ xhi, __nv_bfloat16* __restrict__ xlo,
                          __nv_bfloat16* __restrict__ whi, __nv_bfloat16* __restrict__ wlo,
                          int n4x, int n4w)
{
    const int which = blockIdx.y;
    const float* in;
    __nv_bfloat16 *hi, *lo;
    int n4;
    if (which == 0) { in = x;  hi = xhi; lo = xlo; n4 = n4x; }
    else {
        const float* src[4] = {w0, w1, w2, w3};
        in = src[which - 1];
        hi = whi + (size_t)(which - 1) * H_ * H_;
        lo = wlo + (size_t)(which - 1) * H_ * H_;
        n4 = n4w;
    }
    int i = blockIdx.x * blockDim.x + threadIdx.x;
    int stride = gridDim.x * blockDim.x;
    for (; i < n4; i += stride) {
        float4 v = ((const float4*)in)[i];
        __nv_bfloat16 h0,h1,h2,h3,l0,l1,l2,l3;
        split1(v.x,h0,l0); split1(v.y,h1,l1); split1(v.z,h2,l2); split1(v.w,h3,l3);
        ((__nv_bfloat162*)hi)[2*i+0] = __nv_bfloat162(h0,h1);
        ((__nv_bfloat162*)hi)[2*i+1] = __nv_bfloat162(h2,h3);
        ((__nv_bfloat162*)lo)[2*i+0] = __nv_bfloat162(l0,l1);
        ((__nv_bfloat162*)lo)[2*i+1] = __nv_bfloat162(l2,l3);
    }
}

// ---------------------------------------------------------------------------
// PTX helpers
// ---------------------------------------------------------------------------
__device__ __forceinline__ uint32_t smem_u32(const void* p) {
    uint32_t a;
    asm("{ .reg .u64 t; cvta.to.shared.u64 t, %1; cvt.u32.u64 %0, t; }" : "=r"(a) : "l"(p));
    return a;
}
__device__ __forceinline__ void cp16(uint32_t s, const void* g) {
    asm volatile("cp.async.cg.shared.global [%0], [%1], 16;\n" :: "r"(s), "l"(g));
}
__device__ __forceinline__ void cp_commit() { asm volatile("cp.async.commit_group;\n"); }
template<int N> __device__ __forceinline__ void cp_wait() {
    asm volatile("cp.async.wait_group %0;\n" :: "n"(N));
}
__device__ __forceinline__ void mma16816(float* d, const uint32_t* a, const uint32_t* b) {
    asm volatile("mma.sync.aligned.m16n8k16.row.col.f32.bf16.bf16.f32 "
                 "{%0,%1,%2,%3}, {%4,%5,%6,%7}, {%8,%9}, {%0,%1,%2,%3};\n"
                 : "+f"(d[0]), "+f"(d[1]), "+f"(d[2]), "+f"(d[3])
                 : "r"(a[0]), "r"(a[1]), "r"(a[2]), "r"(a[3]), "r"(b[0]), "r"(b[1]));
}
__device__ __forceinline__ void mma16816h(float* d, const uint32_t* a, const uint32_t* b) {
    asm volatile("mma.sync.aligned.m16n8k16.row.col.f32.f16.f16.f32 "
                 "{%0,%1,%2,%3}, {%4,%5,%6,%7}, {%8,%9}, {%0,%1,%2,%3};\n"
                 : "+f"(d[0]), "+f"(d[1]), "+f"(d[2]), "+f"(d[3])
                 : "r"(a[0]), "r"(a[1]), "r"(a[2]), "r"(a[3]), "r"(b[0]), "r"(b[1]));
}
__device__ __forceinline__ void ldsm4(uint32_t* r, uint32_t a) {
    asm volatile("ldmatrix.sync.aligned.m8n8.x4.shared.b16 {%0,%1,%2,%3}, [%4];"
                 : "=r"(r[0]), "=r"(r[1]), "=r"(r[2]), "=r"(r[3]) : "r"(a));
}
__device__ __forceinline__ void ldsm4t(uint32_t* r, uint32_t a) {
    asm volatile("ldmatrix.sync.aligned.m8n8.x4.trans.shared.b16 {%0,%1,%2,%3}, [%4];"
                 : "=r"(r[0]), "=r"(r[1]), "=r"(r[2]), "=r"(r[3]) : "r"(a));
}
__device__ __forceinline__ uint32_t packh(float a, float b) {
    __half2 h = __floats2half2_rn(a, b);
    return *(uint32_t*)&h;
}

// ---------------------------------------------------------------------------
// bf16x3 GEMM (NT): C = A * W^T + bias — R10 shape (proven config).
// BM=BN=128, BK=32, 256 threads (8 warps 2x4), warp tile 64x32, ldmatrix.
// MODE 0: QKV fused via blockIdx.z; z=0,1 -> bf16 hi/lo out; z=2 -> fp16 hi/lo.
// MODE 1: fp32 out [M,N].
// ---------------------------------------------------------------------------
#define GSTRIDE 40
#define TILE_ELEMS (128*GSTRIDE)
#define STAGE_ELEMS (4*TILE_ELEMS)
#define GEMM_SMEM_BYTES (2*STAGE_ELEMS*2)

template<int MODE>
__global__ __launch_bounds__(256) void gemm_bf16x3(
    const __nv_bfloat16* __restrict__ Ahi, const __nv_bfloat16* __restrict__ Alo,
    const __nv_bfloat16* __restrict__ Wh_base, const __nv_bfloat16* __restrict__ Wl_base,
    const float* __restrict__ bias0, const float* __restrict__ bias1,
    const float* __restrict__ bias2, float scale0,
    float* __restrict__ outf,
    __nv_bfloat16* __restrict__ oh0, __nv_bfloat16* __restrict__ ol0,
    __nv_bfloat16* __restrict__ oh1, __nv_bfloat16* __restrict__ ol1,
    __half* __restrict__ oh2, __half* __restrict__ ol2)
{
    __nv_bfloat16* sm = (__nv_bfloat16*)sm_raw;
    const int K = H_;
    const int tid  = threadIdx.x;
    const int lane = tid & 31, warp = tid >> 5;
    const int g = lane >> 2, tg = lane & 3;
    const int wm = (warp >> 2) * 64, wn = (warp & 3) * 32;
    const int bm = blockIdx.y * 128, bn = blockIdx.x * 128;
    const int z = (MODE == 0) ? blockIdx.z : 0;

    const __nv_bfloat16* Whi = Wh_base + (size_t)z * H_ * H_;
    const __nv_bfloat16* Wlo = Wl_base + (size_t)z * H_ * H_;
    const float* bias = (z == 0) ? bias0 : (z == 1) ? bias1 : bias2;
    const float scale = (MODE == 0 && z == 0) ? scale0 : 1.f;

    const uint32_t sbase = smem_u32(sm);
    const int lrow0 = tid >> 2;
    const int lc8   = (tid & 3) * 8;
    const __nv_bfloat16* gA = Ahi + (size_t)(bm + lrow0) * K + lc8;
    const __nv_bfloat16* gAl= Alo + (size_t)(bm + lrow0) * K + lc8;
    const __nv_bfloat16* gW = Whi + (size_t)(bn + lrow0) * K + lc8;
    const __nv_bfloat16* gWl= Wlo + (size_t)(bn + lrow0) * K + lc8;
    const uint32_t soff0 = (uint32_t)(lrow0 * GSTRIDE + lc8) * 2;
    const uint32_t srowadd = 64 * GSTRIDE * 2;

    auto issue = [&](int kt, int buf) {
        const int k0 = kt * 32;
        uint32_t sb = sbase + buf * (STAGE_ELEMS * 2);
        #pragma unroll
        for (int t = 0; t < 2; t++) {
            uint32_t so = soff0 + t * srowadd;
            size_t go = (size_t)t * 64 * K + k0;
            cp16(sb + 0*TILE_ELEMS*2 + so, gA  + go);
            cp16(sb + 1*TILE_ELEMS*2 + so, gAl + go);
            cp16(sb + 2*TILE_ELEMS*2 + so, gW  + go);
            cp16(sb + 3*TILE_ELEMS*2 + so, gWl + go);
        }
        cp_commit();
    };

    float acc[4][4][4] = {};
    issue(0, 0);
    issue(1, 1);

    const int sub = lane & 7;
    const uint32_t a_off = ((uint32_t)((8 * ((lane >> 3) & 1) + sub) * GSTRIDE
                                       + (lane >> 4) * 8)) * 2;
    const uint32_t b_off = ((uint32_t)((8 * (lane >> 4) + sub) * GSTRIDE
                                       + ((lane >> 3) & 1) * 8)) * 2;

    const int NT = K / 32;
    for (int kt = 0; kt < NT; kt++) {
        if (kt < NT - 1) cp_wait<1>(); else cp_wait<0>();
        __syncthreads();

        const uint32_t stb = sbase + (kt & 1) * (STAGE_ELEMS * 2);

        #pragma unroll
        for (int kh = 0; kh < 32; kh += 16) {
            const uint32_t Aaddr = stb + a_off + (uint32_t)(wm * GSTRIDE + kh) * 2;
            const uint32_t Baddr = stb + 2*TILE_ELEMS*2 + b_off
                                 + (uint32_t)(wn * GSTRIDE + kh) * 2;
            uint32_t afh[4][4], afl[4][4], bhh[2][4], bll[2][4];
            #pragma unroll
            for (int mi = 0; mi < 4; mi++)
                ldsm4(afh[mi], Aaddr + (uint32_t)(mi * 16 * GSTRIDE) * 2);
            ldsm4(bhh[0], Baddr);
            ldsm4(bhh[1], Baddr + (uint32_t)(16 * GSTRIDE) * 2);
            #pragma unroll
            for (int mi = 0; mi < 4; mi++)
                #pragma unroll
                for (int ni = 0; ni < 4; ni++)
                    mma16816(acc[mi][ni], afh[mi], bhh[ni >> 1] + (ni & 1) * 2);
            ldsm4(bll[0], Baddr + TILE_ELEMS*2);
            ldsm4(bll[1], Baddr + TILE_ELEMS*2 + (uint32_t)(16 * GSTRIDE) * 2);
            #pragma unroll
            for (int mi = 0; mi < 4; mi++)
                #pragma unroll
                for (int ni = 0; ni < 4; ni++)
                    mma16816(acc[mi][ni], afh[mi], bll[ni >> 1] + (ni & 1) * 2);
            #pragma unroll
            for (int mi = 0; mi < 4; mi++)
                ldsm4(afl[mi], Aaddr + TILE_ELEMS*2 + (uint32_t)(mi * 16 * GSTRIDE) * 2);
            #pragma unroll
            for (int mi = 0; mi < 4; mi++)
                #pragma unroll
                for (int ni = 0; ni < 4; ni++)
                    mma16816(acc[mi][ni], afl[mi], bhh[ni >> 1] + (ni & 1) * 2);
        }
        __syncthreads();
        if (kt + 2 < NT) issue(kt + 2, kt & 1);
    }

    // epilogue
    #pragma unroll
    for (int ni = 0; ni < 4; ni++) {
        const int n0 = bn + wn + ni * 8 + 2 * tg;
        const float b0 = bias[n0], b1 = bias[n0 + 1];
        #pragma unroll
        for (int mi = 0; mi < 4; mi++) {
            #pragma unroll
            for (int h = 0; h < 2; h++) {
                const int row = bm + wm + mi * 16 + g + h * 8;
                float vx = acc[mi][ni][2*h+0] + b0;
                float vy = acc[mi][ni][2*h+1] + b1;
                if (MODE == 1) {
                    *(float2*)(outf + (size_t)row * H_ + n0) = make_float2(vx, vy);
                } else {
                    vx *= scale; vy *= scale;
                    const int b  = row >> 11;
                    const int s  = row & 2047;
                    const int hd = n0 >> 7;
                    const int dd = n0 & 127;
                    size_t idx = ((size_t)(b * NH + hd) * S_ + s) * HD + dd;
                    if (z == 2) {
                        __half hx, hy, lx, ly;
                        split1h(vx, hx, lx); split1h(vy, hy, ly);
                        *(__half2*)(oh2 + idx) = __halves2half2(hx, hy);
                        *(__half2*)(ol2 + idx) = __halves2half2(lx, ly);
                    } else {
                        __nv_bfloat16* outhi = (z == 0) ? oh0 : oh1;
                        __nv_bfloat16* outlo = (z == 0) ? ol0 : ol1;
                        __nv_bfloat16 hx, hy, lx, ly;
                        split1(vx, hx, lx); split1(vy, hy, ly);
                        *(__nv_bfloat162*)(outhi + idx) = __nv_bfloat162(hx, hy);
                        *(__nv_bfloat162*)(outlo + idx) = __nv_bfloat162(lx, ly);
                    }
                }
            }
        }
    }
}

// ---------------------------------------------------------------------------
// Flash attention v4: PV in fp16 — P single fp16, V fp16 hi/lo, 2-term PV.
// QK^T stays bf16x3.
// ---------------------------------------------------------------------------
#define FV_K(st) ((st)*17408)
#define FV_V(st) (34816 + (st)*17408)
#define FV_SMEM_BYTES (69632*2)

__global__ __launch_bounds__(256) void flash_attn_v4(
    const __nv_bfloat16* __restrict__ Qhi, const __nv_bfloat16* __restrict__ Qlo,
    const __nv_bfloat16* __restrict__ Khi, const __nv_bfloat16* __restrict__ Klo,
    const __half* __restrict__ Vhi, const __half* __restrict__ Vlo,
    __nv_bfloat16* __restrict__ Chi, __nv_bfloat16* __restrict__ Clo)
{
    __nv_bfloat16* sm = (__nv_bfloat16*)sm_raw;
    const int tid = threadIdx.x, lane = tid & 31, w = tid >> 5;
    const int g = lane >> 2, tg = lane & 3;
    const int bh = blockIdx.y, b = bh >> 4, head = bh & 15;
    const int q0 = (NQ - 1 - (int)blockIdx.x) * 128;
    const size_t base = (size_t)bh * S_ * HD;
    const uint32_t sb = smem_u32(sm);
    const int nt = q0 / 64 + 2;

    const int sub   = lane & 7;
    const int halfb = (lane >> 3) & 1;
    const int grpb  = lane >> 4;

    auto issueKV = [&](int kt, int st) {
        const int k0 = kt * 64;
        const uint32_t kb = sb + FV_K(st) * 2;
        const uint32_t vb = sb + FV_V(st) * 2;
        #pragma unroll
        for (int p = 0; p < 4; p++) {
            const int ch = tid + p * 256;
            const int r = ch >> 4, c8 = (ch & 15) * 8;
            const uint32_t off = (uint32_t)(r * 136 + c8) * 2;
            const size_t go = base + (size_t)(k0 + r) * HD + c8;
            cp16(kb + off,          Khi + go);
            cp16(kb + 17408 + off,  Klo + go);
            cp16(vb + off,          Vhi + go);
            cp16(vb + 17408 + off,  Vlo + go);
        }
        cp_commit();
    };

    issueKV(0, 0);

    uint32_t qh[8][4], ql[8][4];
    {
        const size_t r0g = base + (size_t)(q0 + w * 16 + g) * HD;
        #pragma unroll
        for (int kk = 0; kk < 8; kk++) {
            const int c = kk * 16 + 2 * tg;
            qh[kk][0] = *(const uint32_t*)(Qhi + r0g + c);
            qh[kk][1] = *(const uint32_t*)(Qhi + r0g + 8 * HD + c);
            qh[kk][2] = *(const uint32_t*)(Qhi + r0g + c + 8);
            qh[kk][3] = *(const uint32_t*)(Qhi + r0g + 8 * HD + c + 8);
            ql[kk][0] = *(const uint32_t*)(Qlo + r0g + c);
            ql[kk][1] = *(const uint32_t*)(Qlo + r0g + 8 * HD + c);
            ql[kk][2] = *(const uint32_t*)(Qlo + r0g + c + 8);
            ql[kk][3] = *(const uint32_t*)(Qlo + r0g + 8 * HD + c + 8);
        }
    }

    float oacc[16][4] = {};
    float m0 = -1e30f, m1 = -1e30f, l0 = 0.f, l1 = 0.f;
    const int r0 = q0 + w * 16 + g;

    const uint32_t kfragoff = (uint32_t)((8 * grpb + sub) * 136 + halfb * 8) * 2;
    const uint32_t vfragoff = (uint32_t)((8 * halfb + sub) * 136 + 8 * grpb) * 2;

    for (int kt = 0; kt < nt; kt++) {
        const int st = kt & 1;
        __syncthreads();
        if (kt + 1 < nt) { issueKV(kt + 1, st ^ 1); cp_wait<1>(); }
        else             { cp_wait<0>(); }
        __syncthreads();

        // ---- S = Q K^T (bf16x3) ----
        float sacc[8][4];
        #pragma unroll
        for (int j = 0; j < 8; j++)
            sacc[j][0] = sacc[j][1] = sacc[j][2] = sacc[j][3] = 0.f;
        const uint32_t kbase = sb + FV_K(st) * 2 + kfragoff;
        #pragma unroll
        for (int kk = 0; kk < 8; kk++) {
            #pragma unroll
            for (int jp = 0; jp < 4; jp++) {
                uint32_t bh4[4], bl4[4];
                const uint32_t ka = kbase + (uint32_t)(16 * jp * 136 + kk * 16) * 2;
                ldsm4(bh4, ka);
                ldsm4(bl4, ka + 17408);
                mma16816(sacc[2*jp],   qh[kk], bh4);
                mma16816(sacc[2*jp+1], qh[kk], bh4 + 2);
                mma16816(sacc[2*jp],   qh[kk], bl4);
                mma16816(sacc[2*jp+1], qh[kk], bl4 + 2);
                mma16816(sacc[2*jp],   ql[kk], bh4);
                mma16816(sacc[2*jp+1], ql[kk], bh4 + 2);
            }
        }

        // ---- causal mask ----
        const int k0 = kt * 64;
        if (k0 + 63 > r0) {
            #pragma unroll
            for (int j = 0; j < 8; j++) {
                const int c = k0 + j * 8 + 2 * tg;
                if (c     > r0)     sacc[j][0] = -1e30f;
                if (c + 1 > r0)     sacc[j][1] = -1e30f;
                if (c     > r0 + 8) sacc[j][2] = -1e30f;
                if (c + 1 > r0 + 8) sacc[j][3] = -1e30f;
            }
        }

        // ---- online softmax (P single fp16) ----
        float rx0 = -1e30f, rx1 = -1e30f;
        #pragma unroll
        for (int j = 0; j < 8; j++) {
            rx0 = fmaxf(rx0, fmaxf(sacc[j][0], sacc[j][1]));
            rx1 = fmaxf(rx1, fmaxf(sacc[j][2], sacc[j][3]));
        }
        rx0 = fmaxf(rx0, __shfl_xor_sync(0xffffffffu, rx0, 1));
        rx0 = fmaxf(rx0, __shfl_xor_sync(0xffffffffu, rx0, 2));
        rx1 = fmaxf(rx1, __shfl_xor_sync(0xffffffffu, rx1, 1));
        rx1 = fmaxf(rx1, __shfl_xor_sync(0xffffffffu, rx1, 2));
        const float mn0 = fmaxf(m0, rx0), mn1 = fmaxf(m1, rx1);
        const float c0 = __expf(m0 - mn0), c1 = __expf(m1 - mn1);

        uint32_t ph0[8], ph1[8];
        float sum0 = 0.f, sum1 = 0.f;
        #pragma unroll
        for (int j = 0; j < 8; j++) {
            float p00 = __expf(sacc[j][0] - mn0);
            float p01 = __expf(sacc[j][1] - mn0);
            float p10 = __expf(sacc[j][2] - mn1);
            float p11 = __expf(sacc[j][3] - mn1);
            sum0 += p00 + p01;  sum1 += p10 + p11;
            ph0[j] = packh(p00, p01);
            ph1[j] = packh(p10, p11);
        }
        sum0 += __shfl_xor_sync(0xffffffffu, sum0, 1);
        sum0 += __shfl_xor_sync(0xffffffffu, sum0, 2);
        sum1 += __shfl_xor_sync(0xffffffffu, sum1, 1);
        sum1 += __shfl_xor_sync(0xffffffffu, sum1, 2);
        l0 = l0 * c0 + sum0;  m0 = mn0;
        l1 = l1 * c1 + sum1;  m1 = mn1;
        #pragma unroll
        for (int jd = 0; jd < 16; jd++) {
            oacc[jd][0] *= c0; oacc[jd][1] *= c0;
            oacc[jd][2] *= c1; oacc[jd][3] *= c1;
        }

        // ---- O += P V (fp16, 2 terms; V via ldmatrix.trans) ----
        const uint32_t vbase = sb + FV_V(st) * 2 + vfragoff;
        #pragma unroll
        for (int kk2 = 0; kk2 < 4; kk2++) {
            uint32_t a_h[4] = { ph0[2*kk2], ph1[2*kk2], ph0[2*kk2+1], ph1[2*kk2+1] };
            #pragma unroll
            for (int jdp = 0; jdp < 8; jdp++) {
                uint32_t vh4[4], vl4[4];
                const uint32_t va = vbase + (uint32_t)(16 * kk2 * 136 + 16 * jdp) * 2;
                ldsm4t(vh4, va);
                ldsm4t(vl4, va + 17408);
                mma16816h(oacc[2*jdp],   a_h, vh4);
                mma16816h(oacc[2*jdp+1], a_h, vh4 + 2);
                mma16816h(oacc[2*jdp],   a_h, vl4);
                mma16816h(oacc[2*jdp+1], a_h, vl4 + 2);
            }
        }
    }

    // ---- epilogue ----
    const float i0 = 1.f / l0, i1 = 1.f / l1;
    #pragma unroll
    for (int jd = 0; jd < 16; jd++) {
        const int d = jd * 8 + 2 * tg;
        const float o00 = oacc[jd][0] * i0, o01 = oacc[jd][1] * i0;
        const float o10 = oacc[jd][2] * i1, o11 = oacc[jd][3] * i1;
        const size_t idx0 = ((size_t)b * S_ + r0)     * H_ + head * HD + d;
        const size_t idx1 = ((size_t)b * S_ + r0 + 8) * H_ + head * HD + d;
        __nv_bfloat16 hx, hy, lx, ly;
        split1(o00, hx, lx); split1(o01, hy, ly);
        *(__nv_bfloat162*)(Chi + idx0) = __nv_bfloat162(hx, hy);
        *(__nv_bfloat162*)(Clo + idx0) = __nv_bfloat162(lx, ly);
        split1(o10, hx, lx); split1(o11, hy, ly);
        *(__nv_bfloat162*)(Chi + idx1) = __nv_bfloat162(hx, hy);
        *(__nv_bfloat162*)(Clo + idx1) = __nv_bfloat162(lx, ly);
    }
}

// ---------------------------------------------------------------------------
extern "C" void kernel_launch(void* const* d_in, const int* in_sizes, int n_in,
                              void* d_out, int out_size)
{
    const float* x  = (const float*)d_in[0];
    const float* wq = (const float*)d_in[1];
    const float* bq = (const float*)d_in[2];
    const float* wk = (const float*)d_in[3];
    const float* bk = (const float*)d_in[4];
    const float* wv = (const float*)d_in[5];
    const float* bv = (const float*)d_in[6];
    const float* wo = (const float*)d_in[7];
    const float* bo = (const float*)d_in[8];
    float* out = (float*)d_out;

    __nv_bfloat16 *xhi, *xlo, *whi, *wlo;
    __nv_bfloat16 *qhi, *qlo, *khi, *klo, *chi, *clo;
    __half *vhi, *vlo;
    cudaGetSymbolAddress((void**)&xhi, g_xhi);
    cudaGetSymbolAddress((void**)&xlo, g_xlo);
    cudaGetSymbolAddress((void**)&whi, g_whi);
    cudaGetSymbolAddress((void**)&wlo, g_wlo);
    cudaGetSymbolAddress((void**)&qhi, g_qhi);
    cudaGetSymbolAddress((void**)&qlo, g_qlo);
    cudaGetSymbolAddress((void**)&khi, g_khi);
    cudaGetSymbolAddress((void**)&klo, g_klo);
    cudaGetSymbolAddress((void**)&vhi, g_vhi);
    cudaGetSymbolAddress((void**)&vlo, g_vlo);
    cudaGetSymbolAddress((void**)&chi, g_chi);
    cudaGetSymbolAddress((void**)&clo, g_clo);

    static bool attr_set = false;
    if (!attr_set) {
        cudaFuncSetAttribute(gemm_bf16x3<0>, cudaFuncAttributeMaxDynamicSharedMemorySize, GEMM_SMEM_BYTES);
        cudaFuncSetAttribute(gemm_bf16x3<1>, cudaFuncAttributeMaxDynamicSharedMemorySize, GEMM_SMEM_BYTES);
        cudaFuncSetAttribute(flash_attn_v4, cudaFuncAttributeMaxDynamicSharedMemorySize, FV_SMEM_BYTES);
        attr_set = true;
    }

    const float qscale = 0.08838834764831845f;   // 1/sqrt(128)

    // Fused split: y=0 -> x (M*H elems), y=1..4 -> weights (H*H each)
    split_all<<<dim3(256, 5), 256>>>(x, wq, wk, wv, wo, xhi, xlo, whi, wlo,
                                     M_*H_/4, H_*H_/4);

    // Fused QKV projection (z selects Q/K/V; V emits fp16 pairs)
    dim3 gqkv(H_/128, M_/128, 3);   // (16, 32, 3)
    gemm_bf16x3<0><<<gqkv, 256, GEMM_SMEM_BYTES>>>(
        xhi, xlo, whi, wlo, bq, bk, bv, qscale, nullptr,
        qhi, qlo, khi, klo, vhi, vlo);

    dim3 gf(NQ, B_*NH);   // (16, 32)
    flash_attn_v4<<<gf, 256, FV_SMEM_BYTES>>>(qhi, qlo, khi, klo, vhi, vlo, chi, clo);

    // Output projection (weight slot 3)
    dim3 gg(H_/128, M_/128);
    gemm_bf16x3<1><<<gg, 256, GEMM_SMEM_BYTES>>>(
        chi, clo, whi + 3*(size_t)H_*H_, wlo + 3*(size_t)H_*H_,
        bo, bo, bo, 1.f, out,
        nullptr, nullptr, nullptr, nullptr, nullptr, nullptr);
}

// round 14
// speedup vs baseline: 1.4879x; 1.2911x over previous
#include <cuda_runtime.h>
#include <cuda_bf16.h>
#include <cuda_fp16.h>
#include <cstdint>

#define B_  2
#define S_  2048
#define H_  2048
#define NH  16
#define HD  128
#define M_  (B_*S_)
#define NQ  (S_/128)

extern __shared__ __align__(16) unsigned char sm_raw[];

// ---------------------------------------------------------------------------
// Scratch
// ---------------------------------------------------------------------------
__device__ __half        g_xh [(size_t)M_*H_];    // x, single fp16
__device__ __half        g_wh [4][(size_t)H_*H_]; // weights fp16 hi
__device__ __half        g_wl [4][(size_t)H_*H_]; // weights fp16 lo
__device__ __nv_bfloat16 g_qhi[(size_t)M_*H_];    // [b,h,s,d], pre-scaled
__device__ __nv_bfloat16 g_qlo[(size_t)M_*H_];
__device__ __nv_bfloat16 g_khi[(size_t)M_*H_];    // [b,h,s,d]
__device__ __nv_bfloat16 g_klo[(size_t)M_*H_];
__device__ __half        g_vhi[(size_t)M_*H_];    // [b,h,s,d]
__device__ __half        g_vlo[(size_t)M_*H_];
__device__ __half        g_ch [(size_t)M_*H_];    // ctx [b,s,h], single fp16

// ---------------------------------------------------------------------------
__device__ __forceinline__ void split1(float v, __nv_bfloat16& h, __nv_bfloat16& l) {
    h = __float2bfloat16(v);
    l = __float2bfloat16(v - __bfloat162float(h));
}
__device__ __forceinline__ void split1h(float v, __half& h, __half& l) {
    h = __float2half_rn(v);
    l = __float2half_rn(v - __half2float(h));
}

// Fused splitter: y=0 -> x single fp16 (n4x); y=1..4 -> weights fp16 hi/lo (n4w)
__global__ void split_all(const float* __restrict__ x,
                          const float* __restrict__ w0, const float* __restrict__ w1,
                          const float* __restrict__ w2, const float* __restrict__ w3,
                          __half* __restrict__ xh,
                          __half* __restrict__ wh, __half* __restrict__ wl,
                          int n4x, int n4w)
{
    const int which = blockIdx.y;
    int i = blockIdx.x * blockDim.x + threadIdx.x;
    int stride = gridDim.x * blockDim.x;
    if (which == 0) {
        for (; i < n4x; i += stride) {
            float4 v = ((const float4*)x)[i];
            ((__half2*)xh)[2*i+0] = __floats2half2_rn(v.x, v.y);
            ((__half2*)xh)[2*i+1] = __floats2half2_rn(v.z, v.w);
        }
    } else {
        const float* src[4] = {w0, w1, w2, w3};
        const float* in = src[which - 1];
        __half* hi = wh + (size_t)(which - 1) * H_ * H_;
        __half* lo = wl + (size_t)(which - 1) * H_ * H_;
        for (; i < n4w; i += stride) {
            float4 v = ((const float4*)in)[i];
            __half h0,h1,h2,h3,l0,l1,l2,l3;
            split1h(v.x,h0,l0); split1h(v.y,h1,l1); split1h(v.z,h2,l2); split1h(v.w,h3,l3);
            ((__half2*)hi)[2*i+0] = __halves2half2(h0,h1);
            ((__half2*)hi)[2*i+1] = __halves2half2(h2,h3);
            ((__half2*)lo)[2*i+0] = __halves2half2(l0,l1);
            ((__half2*)lo)[2*i+1] = __halves2half2(l2,l3);
        }
    }
}

// ---------------------------------------------------------------------------
// PTX helpers
// ---------------------------------------------------------------------------
__device__ __forceinline__ uint32_t smem_u32(const void* p) {
    uint32_t a;
    asm("{ .reg .u64 t; cvta.to.shared.u64 t, %1; cvt.u32.u64 %0, t; }" : "=r"(a) : "l"(p));
    return a;
}
__device__ __forceinline__ void cp16(uint32_t s, const void* g) {
    asm volatile("cp.async.cg.shared.global [%0], [%1], 16;\n" :: "r"(s), "l"(g));
}
__device__ __forceinline__ void cp_commit() { asm volatile("cp.async.commit_group;\n"); }
template<int N> __device__ __forceinline__ void cp_wait() {
    asm volatile("cp.async.wait_group %0;\n" :: "n"(N));
}
__device__ __forceinline__ void mma16816(float* d, const uint32_t* a, const uint32_t* b) {
    asm volatile("mma.sync.aligned.m16n8k16.row.col.f32.bf16.bf16.f32 "
                 "{%0,%1,%2,%3}, {%4,%5,%6,%7}, {%8,%9}, {%0,%1,%2,%3};\n"
                 : "+f"(d[0]), "+f"(d[1]), "+f"(d[2]), "+f"(d[3])
                 : "r"(a[0]), "r"(a[1]), "r"(a[2]), "r"(a[3]), "r"(b[0]), "r"(b[1]));
}
__device__ __forceinline__ void mma16816h(float* d, const uint32_t* a, const uint32_t* b) {
    asm volatile("mma.sync.aligned.m16n8k16.row.col.f32.f16.f16.f32 "
                 "{%0,%1,%2,%3}, {%4,%5,%6,%7}, {%8,%9}, {%0,%1,%2,%3};\n"
                 : "+f"(d[0]), "+f"(d[1]), "+f"(d[2]), "+f"(d[3])
                 : "r"(a[0]), "r"(a[1]), "r"(a[2]), "r"(a[3]), "r"(b[0]), "r"(b[1]));
}
__device__ __forceinline__ void ldsm4(uint32_t* r, uint32_t a) {
    asm volatile("ldmatrix.sync.aligned.m8n8.x4.shared.b16 {%0,%1,%2,%3}, [%4];"
                 : "=r"(r[0]), "=r"(r[1]), "=r"(r[2]), "=r"(r[3]) : "r"(a));
}
__device__ __forceinline__ void ldsm4t(uint32_t* r, uint32_t a) {
    asm volatile("ldmatrix.sync.aligned.m8n8.x4.trans.shared.b16 {%0,%1,%2,%3}, [%4];"
                 : "=r"(r[0]), "=r"(r[1]), "=r"(r[2]), "=r"(r[3]) : "r"(a));
}
__device__ __forceinline__ uint32_t packh(float a, float b) {
    __half2 h = __floats2half2_rn(a, b);
    return *(uint32_t*)&h;
}

// ---------------------------------------------------------------------------
// fp16x2 GEMM (NT): C = A * W^T + bias; A single fp16, W fp16 hi/lo (2 terms).
// BM=BN=128, BK=32, 256 threads (8 warps 2x4), warp tile 64x32, ldmatrix.
// MODE 0: QKV fused via blockIdx.z; z=0,1 -> bf16 hi/lo out; z=2 -> fp16 hi/lo.
// MODE 1: fp32 out [M,N].
// smem/stage: A 10240, Wh 10240, Wl 10240 = 30720 B; double-buffered.
// ---------------------------------------------------------------------------
#define GSTRIDE 40
#define GT_A 10240
#define GT_STAGE 30720
#define GEMM_SMEM_BYTES (2*GT_STAGE)

template<int MODE>
__global__ __launch_bounds__(256) void gemm_fp16x2(
    const __half* __restrict__ A,
    const __half* __restrict__ Wh_base, const __half* __restrict__ Wl_base,
    const float* __restrict__ bias0, const float* __restrict__ bias1,
    const float* __restrict__ bias2, float scale0,
    float* __restrict__ outf,
    __nv_bfloat16* __restrict__ oh0, __nv_bfloat16* __restrict__ ol0,
    __nv_bfloat16* __restrict__ oh1, __nv_bfloat16* __restrict__ ol1,
    __half* __restrict__ oh2, __half* __restrict__ ol2)
{
    const int K = H_;
    const int tid  = threadIdx.x;
    const int lane = tid & 31, warp = tid >> 5;
    const int g = lane >> 2, tg = lane & 3;
    const int wm = (warp >> 2) * 64, wn = (warp & 3) * 32;
    const int bm = blockIdx.y * 128, bn = blockIdx.x * 128;
    const int z = (MODE == 0) ? blockIdx.z : 0;

    const __half* Wh = Wh_base + (size_t)z * H_ * H_;
    const __half* Wl = Wl_base + (size_t)z * H_ * H_;
    const float* bias = (z == 0) ? bias0 : (z == 1) ? bias1 : bias2;
    const float scale = (MODE == 0 && z == 0) ? scale0 : 1.f;

    const uint32_t sbase = smem_u32(sm_raw);

    auto issue = [&](int kt, int buf) {
        const int k0 = kt * 32;
        const uint32_t sb = sbase + buf * GT_STAGE;
        #pragma unroll
        for (int i = 0; i < 2; i++) {
            const int ch = tid + i * 256;            // 0..511
            const int r = ch >> 2, c16 = ch & 3;
            const uint32_t off = (uint32_t)(r * GSTRIDE + c16 * 8) * 2;
            cp16(sb + off,            A  + (size_t)(bm + r) * K + k0 + c16 * 8);
            cp16(sb + GT_A + off,     Wh + (size_t)(bn + r) * K + k0 + c16 * 8);
            cp16(sb + 2*GT_A + off,   Wl + (size_t)(bn + r) * K + k0 + c16 * 8);
        }
        cp_commit();
    };

    float acc[4][4][4] = {};
    issue(0, 0);
    issue(1, 1);

    const int sub = lane & 7;
    const uint32_t a_off = ((uint32_t)((8 * ((lane >> 3) & 1) + sub) * GSTRIDE
                                       + (lane >> 4) * 8)) * 2;
    const uint32_t b_off = ((uint32_t)((8 * (lane >> 4) + sub) * GSTRIDE
                                       + ((lane >> 3) & 1) * 8)) * 2;

    const int NT = K / 32;
    for (int kt = 0; kt < NT; kt++) {
        if (kt < NT - 1) cp_wait<1>(); else cp_wait<0>();
        __syncthreads();

        const uint32_t stb = sbase + (kt & 1) * GT_STAGE;

        #pragma unroll
        for (int kh = 0; kh < 32; kh += 16) {
            const uint32_t Aaddr = stb + a_off + (uint32_t)(wm * GSTRIDE + kh) * 2;
            const uint32_t Baddr = stb + GT_A + b_off + (uint32_t)(wn * GSTRIDE + kh) * 2;
            uint32_t af[4][4], bh[2][4], bl[2][4];
            #pragma unroll
            for (int mi = 0; mi < 4; mi++)
                ldsm4(af[mi], Aaddr + (uint32_t)(mi * 16 * GSTRIDE) * 2);
            ldsm4(bh[0], Baddr);
            ldsm4(bh[1], Baddr + (uint32_t)(16 * GSTRIDE) * 2);
            #pragma unroll
            for (int mi = 0; mi < 4; mi++)
                #pragma unroll
                for (int ni = 0; ni < 4; ni++)
                    mma16816h(acc[mi][ni], af[mi], bh[ni >> 1] + (ni & 1) * 2);
            ldsm4(bl[0], Baddr + GT_A);
            ldsm4(bl[1], Baddr + GT_A + (uint32_t)(16 * GSTRIDE) * 2);
            #pragma unroll
            for (int mi = 0; mi < 4; mi++)
                #pragma unroll
                for (int ni = 0; ni < 4; ni++)
                    mma16816h(acc[mi][ni], af[mi], bl[ni >> 1] + (ni & 1) * 2);
        }
        __syncthreads();
        if (kt + 2 < NT) issue(kt + 2, kt & 1);
    }

    // epilogue
    #pragma unroll
    for (int ni = 0; ni < 4; ni++) {
        const int n0 = bn + wn + ni * 8 + 2 * tg;
        const float b0 = bias[n0], b1 = bias[n0 + 1];
        #pragma unroll
        for (int mi = 0; mi < 4; mi++) {
            #pragma unroll
            for (int h = 0; h < 2; h++) {
                const int row = bm + wm + mi * 16 + g + h * 8;
                float vx = acc[mi][ni][2*h+0] + b0;
                float vy = acc[mi][ni][2*h+1] + b1;
                if (MODE == 1) {
                    *(float2*)(outf + (size_t)row * H_ + n0) = make_float2(vx, vy);
                } else {
                    vx *= scale; vy *= scale;
                    const int b  = row >> 11;
                    const int s  = row & 2047;
                    const int hd = n0 >> 7;
                    const int dd = n0 & 127;
                    size_t idx = ((size_t)(b * NH + hd) * S_ + s) * HD + dd;
                    if (z == 2) {
                        __half hx, hy, lx, ly;
                        split1h(vx, hx, lx); split1h(vy, hy, ly);
                        *(__half2*)(oh2 + idx) = __halves2half2(hx, hy);
                        *(__half2*)(ol2 + idx) = __halves2half2(lx, ly);
                    } else {
                        __nv_bfloat16* outhi = (z == 0) ? oh0 : oh1;
                        __nv_bfloat16* outlo = (z == 0) ? ol0 : ol1;
                        __nv_bfloat16 hx, hy, lx, ly;
                        split1(vx, hx, lx); split1(vy, hy, ly);
                        *(__nv_bfloat162*)(outhi + idx) = __nv_bfloat162(hx, hy);
                        *(__nv_bfloat162*)(outlo + idx) = __nv_bfloat162(lx, ly);
                    }
                }
            }
        }
    }
}

// ---------------------------------------------------------------------------
// Flash attention v4 (R13): QK^T bf16x3, PV fp16 2-term.
// Epilogue writes ctx as SINGLE fp16.
// ---------------------------------------------------------------------------
#define FV_K(st) ((st)*17408)
#define FV_V(st) (34816 + (st)*17408)
#define FV_SMEM_BYTES (69632*2)

__global__ __launch_bounds__(256) void flash_attn_v4(
    const __nv_bfloat16* __restrict__ Qhi, const __nv_bfloat16* __restrict__ Qlo,
    const __nv_bfloat16* __restrict__ Khi, const __nv_bfloat16* __restrict__ Klo,
    const __half* __restrict__ Vhi, const __half* __restrict__ Vlo,
    __half* __restrict__ Ch)
{
    __nv_bfloat16* sm = (__nv_bfloat16*)sm_raw;
    const int tid = threadIdx.x, lane = tid & 31, w = tid >> 5;
    const int g = lane >> 2, tg = lane & 3;
    const int bh = blockIdx.y, b = bh >> 4, head = bh & 15;
    const int q0 = (NQ - 1 - (int)blockIdx.x) * 128;
    const size_t base = (size_t)bh * S_ * HD;
    const uint32_t sb = smem_u32(sm);
    const int nt = q0 / 64 + 2;

    const int sub   = lane & 7;
    const int halfb = (lane >> 3) & 1;
    const int grpb  = lane >> 4;

    auto issueKV = [&](int kt, int st) {
        const int k0 = kt * 64;
        const uint32_t kb = sb + FV_K(st) * 2;
        const uint32_t vb = sb + FV_V(st) * 2;
        #pragma unroll
        for (int p = 0; p < 4; p++) {
            const int ch = tid + p * 256;
            const int r = ch >> 4, c8 = (ch & 15) * 8;
            const uint32_t off = (uint32_t)(r * 136 + c8) * 2;
            const size_t go = base + (size_t)(k0 + r) * HD + c8;
            cp16(kb + off,          Khi + go);
            cp16(kb + 17408 + off,  Klo + go);
            cp16(vb + off,          Vhi + go);
            cp16(vb + 17408 + off,  Vlo + go);
        }
        cp_commit();
    };

    issueKV(0, 0);

    uint32_t qh[8][4], ql[8][4];
    {
        const size_t r0g = base + (size_t)(q0 + w * 16 + g) * HD;
        #pragma unroll
        for (int kk = 0; kk < 8; kk++) {
            const int c = kk * 16 + 2 * tg;
            qh[kk][0] = *(const uint32_t*)(Qhi + r0g + c);
            qh[kk][1] = *(const uint32_t*)(Qhi + r0g + 8 * HD + c);
            qh[kk][2] = *(const uint32_t*)(Qhi + r0g + c + 8);
            qh[kk][3] = *(const uint32_t*)(Qhi + r0g + 8 * HD + c + 8);
            ql[kk][0] = *(const uint32_t*)(Qlo + r0g + c);
            ql[kk][1] = *(const uint32_t*)(Qlo + r0g + 8 * HD + c);
            ql[kk][2] = *(const uint32_t*)(Qlo + r0g + c + 8);
            ql[kk][3] = *(const uint32_t*)(Qlo + r0g + 8 * HD + c + 8);
        }
    }

    float oacc[16][4] = {};
    float m0 = -1e30f, m1 = -1e30f, l0 = 0.f, l1 = 0.f;
    const int r0 = q0 + w * 16 + g;

    const uint32_t kfragoff = (uint32_t)((8 * grpb + sub) * 136 + halfb * 8) * 2;
    const uint32_t vfragoff = (uint32_t)((8 * halfb + sub) * 136 + 8 * grpb) * 2;

    for (int kt = 0; kt < nt; kt++) {
        const int st = kt & 1;
        __syncthreads();
        if (kt + 1 < nt) { issueKV(kt + 1, st ^ 1); cp_wait<1>(); }
        else             { cp_wait<0>(); }
        __syncthreads();

        // ---- S = Q K^T (bf16x3) ----
        float sacc[8][4];
        #pragma unroll
        for (int j = 0; j < 8; j++)
            sacc[j][0] = sacc[j][1] = sacc[j][2] = sacc[j][3] = 0.f;
        const uint32_t kbase = sb + FV_K(st) * 2 + kfragoff;
        #pragma unroll
        for (int kk = 0; kk < 8; kk++) {
            #pragma unroll
            for (int jp = 0; jp < 4; jp++) {
                uint32_t bh4[4], bl4[4];
                const uint32_t ka = kbase + (uint32_t)(16 * jp * 136 + kk * 16) * 2;
                ldsm4(bh4, ka);
                ldsm4(bl4, ka + 17408);
                mma16816(sacc[2*jp],   qh[kk], bh4);
                mma16816(sacc[2*jp+1], qh[kk], bh4 + 2);
                mma16816(sacc[2*jp],   qh[kk], bl4);
                mma16816(sacc[2*jp+1], qh[kk], bl4 + 2);
                mma16816(sacc[2*jp],   ql[kk], bh4);
                mma16816(sacc[2*jp+1], ql[kk], bh4 + 2);
            }
        }

        // ---- causal mask ----
        const int k0 = kt * 64;
        if (k0 + 63 > r0) {
            #pragma unroll
            for (int j = 0; j < 8; j++) {
                const int c = k0 + j * 8 + 2 * tg;
                if (c     > r0)     sacc[j][0] = -1e30f;
                if (c + 1 > r0)     sacc[j][1] = -1e30f;
                if (c     > r0 + 8) sacc[j][2] = -1e30f;
                if (c + 1 > r0 + 8) sacc[j][3] = -1e30f;
            }
        }

        // ---- online softmax (P single fp16) ----
        float rx0 = -1e30f, rx1 = -1e30f;
        #pragma unroll
        for (int j = 0; j < 8; j++) {
            rx0 = fmaxf(rx0, fmaxf(sacc[j][0], sacc[j][1]));
            rx1 = fmaxf(rx1, fmaxf(sacc[j][2], sacc[j][3]));
        }
        rx0 = fmaxf(rx0, __shfl_xor_sync(0xffffffffu, rx0, 1));
        rx0 = fmaxf(rx0, __shfl_xor_sync(0xffffffffu, rx0, 2));
        rx1 = fmaxf(rx1, __shfl_xor_sync(0xffffffffu, rx1, 1));
        rx1 = fmaxf(rx1, __shfl_xor_sync(0xffffffffu, rx1, 2));
        const float mn0 = fmaxf(m0, rx0), mn1 = fmaxf(m1, rx1);
        const float c0 = __expf(m0 - mn0), c1 = __expf(m1 - mn1);

        uint32_t ph0[8], ph1[8];
        float sum0 = 0.f, sum1 = 0.f;
        #pragma unroll
        for (int j = 0; j < 8; j++) {
            float p00 = __expf(sacc[j][0] - mn0);
            float p01 = __expf(sacc[j][1] - mn0);
            float p10 = __expf(sacc[j][2] - mn1);
            float p11 = __expf(sacc[j][3] - mn1);
            sum0 += p00 + p01;  sum1 += p10 + p11;
            ph0[j] = packh(p00, p01);
            ph1[j] = packh(p10, p11);
        }
        sum0 += __shfl_xor_sync(0xffffffffu, sum0, 1);
        sum0 += __shfl_xor_sync(0xffffffffu, sum0, 2);
        sum1 += __shfl_xor_sync(0xffffffffu, sum1, 1);
        sum1 += __shfl_xor_sync(0xffffffffu, sum1, 2);
        l0 = l0 * c0 + sum0;  m0 = mn0;
        l1 = l1 * c1 + sum1;  m1 = mn1;
        #pragma unroll
        for (int jd = 0; jd < 16; jd++) {
            oacc[jd][0] *= c0; oacc[jd][1] *= c0;
            oacc[jd][2] *= c1; oacc[jd][3] *= c1;
        }

        // ---- O += P V (fp16, 2 terms) ----
        const uint32_t vbase = sb + FV_V(st) * 2 + vfragoff;
        #pragma unroll
        for (int kk2 = 0; kk2 < 4; kk2++) {
            uint32_t a_h[4] = { ph0[2*kk2], ph1[2*kk2], ph0[2*kk2+1], ph1[2*kk2+1] };
            #pragma unroll
            for (int jdp = 0; jdp < 8; jdp++) {
                uint32_t vh4[4], vl4[4];
                const uint32_t va = vbase + (uint32_t)(16 * kk2 * 136 + 16 * jdp) * 2;
                ldsm4t(vh4, va);
                ldsm4t(vl4, va + 17408);
                mma16816h(oacc[2*jdp],   a_h, vh4);
                mma16816h(oacc[2*jdp+1], a_h, vh4 + 2);
                mma16816h(oacc[2*jdp],   a_h, vl4);
                mma16816h(oacc[2*jdp+1], a_h, vl4 + 2);
            }
        }
    }

    // ---- epilogue: single fp16 ctx ----
    const float i0 = 1.f / l0, i1 = 1.f / l1;
    #pragma unroll
    for (int jd = 0; jd < 16; jd++) {
        const int d = jd * 8 + 2 * tg;
        const size_t idx0 = ((size_t)b * S_ + r0)     * H_ + head * HD + d;
        const size_t idx1 = ((size_t)b * S_ + r0 + 8) * H_ + head * HD + d;
        *(__half2*)(Ch + idx0) = __floats2half2_rn(oacc[jd][0] * i0, oacc[jd][1] * i0);
        *(__half2*)(Ch + idx1) = __floats2half2_rn(oacc[jd][2] * i1, oacc[jd][3] * i1);
    }
}

// ---------------------------------------------------------------------------
extern "C" void kernel_launch(void* const* d_in, const int* in_sizes, int n_in,
                              void* d_out, int out_size)
{
    const float* x  = (const float*)d_in[0];
    const float* wq = (const float*)d_in[1];
    const float* bq = (const float*)d_in[2];
    const float* wk = (const float*)d_in[3];
    const float* bk = (const float*)d_in[4];
    const float* wv = (const float*)d_in[5];
    const float* bv = (const float*)d_in[6];
    const float* wo = (const float*)d_in[7];
    const float* bo = (const float*)d_in[8];
    float* out = (float*)d_out;

    __half *xh, *wh, *wl, *vhi, *vlo, *ch;
    __nv_bfloat16 *qhi, *qlo, *khi, *klo;
    cudaGetSymbolAddress((void**)&xh,  g_xh);
    cudaGetSymbolAddress((void**)&wh,  g_wh);
    cudaGetSymbolAddress((void**)&wl,  g_wl);
    cudaGetSymbolAddress((void**)&qhi, g_qhi);
    cudaGetSymbolAddress((void**)&qlo, g_qlo);
    cudaGetSymbolAddress((void**)&khi, g_khi);
    cudaGetSymbolAddress((void**)&klo, g_klo);
    cudaGetSymbolAddress((void**)&vhi, g_vhi);
    cudaGetSymbolAddress((void**)&vlo, g_vlo);
    cudaGetSymbolAddress((void**)&ch,  g_ch);

    static bool attr_set = false;
    if (!attr_set) {
        cudaFuncSetAttribute(gemm_fp16x2<0>, cudaFuncAttributeMaxDynamicSharedMemorySize, GEMM_SMEM_BYTES);
        cudaFuncSetAttribute(gemm_fp16x2<1>, cudaFuncAttributeMaxDynamicSharedMemorySize, GEMM_SMEM_BYTES);
        cudaFuncSetAttribute(flash_attn_v4, cudaFuncAttributeMaxDynamicSharedMemorySize, FV_SMEM_BYTES);
        attr_set = true;
    }

    const float qscale = 0.08838834764831845f;   // 1/sqrt(128)

    // Fused split: y=0 -> x (M*H, single fp16), y=1..4 -> weights (H*H, fp16 hi/lo)
    split_all<<<dim3(256, 5), 256>>>(x, wq, wk, wv, wo, xh, wh, wl,
                                     M_*H_/4, H_*H_/4);

    // Fused QKV projection (z selects Q/K/V)
    dim3 gqkv(H_/128, M_/128, 3);   // (16, 32, 3)
    gemm_fp16x2<0><<<gqkv, 256, GEMM_SMEM_BYTES>>>(
        xh, wh, wl, bq, bk, bv, qscale, nullptr,
        qhi, qlo, khi, klo, vhi, vlo);

    dim3 gf(NQ, B_*NH);   // (16, 32)
    flash_attn_v4<<<gf, 256, FV_SMEM_BYTES>>>(qhi, qlo, khi, klo, vhi, vlo, ch);

    // Output projection (weight slot 3); A = ctx single fp16
    dim3 gg(H_/128, M_/128);
    gemm_fp16x2<1><<<gg, 256, GEMM_SMEM_BYTES>>>(
        ch, wh + 3*(size_t)H_*H_, wl + 3*(size_t)H_*H_,
        bo, bo, bo, 1.f, out,
        nullptr, nullptr, nullptr, nullptr, nullptr, nullptr);
}

// round 15
// speedup vs baseline: 1.5803x; 1.0621x over previous
#include <cuda_runtime.h>
#include <cuda_bf16.h>
#include <cuda_fp16.h>
#include <cstdint>

#define B_  2
#define S_  2048
#define H_  2048
#define NH  16
#define HD  128
#define M_  (B_*S_)
#define NQ  (S_/128)

extern __shared__ __align__(16) unsigned char sm_raw[];

// ---------------------------------------------------------------------------
// Scratch
// ---------------------------------------------------------------------------
__device__ __half g_xh [(size_t)M_*H_];    // x, single fp16
__device__ __half g_wh [4][(size_t)H_*H_]; // weights fp16 hi
__device__ __half g_wl [4][(size_t)H_*H_]; // weights fp16 lo
__device__ __half g_qh [(size_t)M_*H_];    // Q single fp16, pre-scaled [b,h,s,d]
__device__ __half g_khi[(size_t)M_*H_];    // K fp16 hi/lo [b,h,s,d]
__device__ __half g_klo[(size_t)M_*H_];
__device__ __half g_vhi[(size_t)M_*H_];    // V fp16 hi/lo [b,h,s,d]
__device__ __half g_vlo[(size_t)M_*H_];
__device__ __half g_ch [(size_t)M_*H_];    // ctx [b,s,h], single fp16

// ---------------------------------------------------------------------------
__device__ __forceinline__ void split1h(float v, __half& h, __half& l) {
    h = __float2half_rn(v);
    l = __float2half_rn(v - __half2float(h));
}

// Fused splitter: y=0 -> x single fp16 (n4x); y=1..4 -> weights fp16 hi/lo (n4w)
__global__ void split_all(const float* __restrict__ x,
                          const float* __restrict__ w0, const float* __restrict__ w1,
                          const float* __restrict__ w2, const float* __restrict__ w3,
                          __half* __restrict__ xh,
                          __half* __restrict__ wh, __half* __restrict__ wl,
                          int n4x, int n4w)
{
    const int which = blockIdx.y;
    int i = blockIdx.x * blockDim.x + threadIdx.x;
    int stride = gridDim.x * blockDim.x;
    if (which == 0) {
        for (; i < n4x; i += stride) {
            float4 v = ((const float4*)x)[i];
            ((__half2*)xh)[2*i+0] = __floats2half2_rn(v.x, v.y);
            ((__half2*)xh)[2*i+1] = __floats2half2_rn(v.z, v.w);
        }
    } else {
        const float* src[4] = {w0, w1, w2, w3};
        const float* in = src[which - 1];
        __half* hi = wh + (size_t)(which - 1) * H_ * H_;
        __half* lo = wl + (size_t)(which - 1) * H_ * H_;
        for (; i < n4w; i += stride) {
            float4 v = ((const float4*)in)[i];
            __half h0,h1,h2,h3,l0,l1,l2,l3;
            split1h(v.x,h0,l0); split1h(v.y,h1,l1); split1h(v.z,h2,l2); split1h(v.w,h3,l3);
            ((__half2*)hi)[2*i+0] = __halves2half2(h0,h1);
            ((__half2*)hi)[2*i+1] = __halves2half2(h2,h3);
            ((__half2*)lo)[2*i+0] = __halves2half2(l0,l1);
            ((__half2*)lo)[2*i+1] = __halves2half2(l2,l3);
        }
    }
}

// ---------------------------------------------------------------------------
// PTX helpers
// ---------------------------------------------------------------------------
__device__ __forceinline__ uint32_t smem_u32(const void* p) {
    uint32_t a;
    asm("{ .reg .u64 t; cvta.to.shared.u64 t, %1; cvt.u32.u64 %0, t; }" : "=r"(a) : "l"(p));
    return a;
}
__device__ __forceinline__ void cp16(uint32_t s, const void* g) {
    asm volatile("cp.async.cg.shared.global [%0], [%1], 16;\n" :: "r"(s), "l"(g));
}
__device__ __forceinline__ void cp_commit() { asm volatile("cp.async.commit_group;\n"); }
template<int N> __device__ __forceinline__ void cp_wait() {
    asm volatile("cp.async.wait_group %0;\n" :: "n"(N));
}
__device__ __forceinline__ void mma16816h(float* d, const uint32_t* a, const uint32_t* b) {
    asm volatile("mma.sync.aligned.m16n8k16.row.col.f32.f16.f16.f32 "
                 "{%0,%1,%2,%3}, {%4,%5,%6,%7}, {%8,%9}, {%0,%1,%2,%3};\n"
                 : "+f"(d[0]), "+f"(d[1]), "+f"(d[2]), "+f"(d[3])
                 : "r"(a[0]), "r"(a[1]), "r"(a[2]), "r"(a[3]), "r"(b[0]), "r"(b[1]));
}
__device__ __forceinline__ void ldsm4(uint32_t* r, uint32_t a) {
    asm volatile("ldmatrix.sync.aligned.m8n8.x4.shared.b16 {%0,%1,%2,%3}, [%4];"
                 : "=r"(r[0]), "=r"(r[1]), "=r"(r[2]), "=r"(r[3]) : "r"(a));
}
__device__ __forceinline__ void ldsm4t(uint32_t* r, uint32_t a) {
    asm volatile("ldmatrix.sync.aligned.m8n8.x4.trans.shared.b16 {%0,%1,%2,%3}, [%4];"
                 : "=r"(r[0]), "=r"(r[1]), "=r"(r[2]), "=r"(r[3]) : "r"(a));
}
__device__ __forceinline__ uint32_t packh(float a, float b) {
    __half2 h = __floats2half2_rn(a, b);
    return *(uint32_t*)&h;
}

// ---------------------------------------------------------------------------
// fp16x2 GEMM (NT): C = A * W^T + bias; A single fp16, W fp16 hi/lo (2 terms).
// BM=BN=128, BK=32, 256 threads, warp tile 64x32, ldmatrix.
// __launch_bounds__(256,2) pins regs <= 128 for 2 CTA/SM.
// MODE 0: QKV fused via blockIdx.z; z=0 -> single fp16 out (Q, *scale);
//         z=1,2 -> fp16 hi/lo out (K, V).
// MODE 1: fp32 out [M,N].
// ---------------------------------------------------------------------------
#define GSTRIDE 40
#define GT_A 10240
#define GT_STAGE 30720
#define GEMM_SMEM_BYTES (2*GT_STAGE)

template<int MODE>
__global__ __launch_bounds__(256, 2) void gemm_fp16x2(
    const __half* __restrict__ A,
    const __half* __restrict__ Wh_base, const __half* __restrict__ Wl_base,
    const float* __restrict__ bias0, const float* __restrict__ bias1,
    const float* __restrict__ bias2, float scale0,
    float* __restrict__ outf,
    __half* __restrict__ oq,
    __half* __restrict__ oh1, __half* __restrict__ ol1,
    __half* __restrict__ oh2, __half* __restrict__ ol2)
{
    const int K = H_;
    const int tid  = threadIdx.x;
    const int lane = tid & 31, warp = tid >> 5;
    const int g = lane >> 2, tg = lane & 3;
    const int wm = (warp >> 2) * 64, wn = (warp & 3) * 32;
    const int bm = blockIdx.y * 128, bn = blockIdx.x * 128;
    const int z = (MODE == 0) ? blockIdx.z : 0;

    const __half* Wh = Wh_base + (size_t)z * H_ * H_;
    const __half* Wl = Wl_base + (size_t)z * H_ * H_;
    const float* bias = (z == 0) ? bias0 : (z == 1) ? bias1 : bias2;
    const float scale = (MODE == 0 && z == 0) ? scale0 : 1.f;

    const uint32_t sbase = smem_u32(sm_raw);

    auto issue = [&](int kt, int buf) {
        const int k0 = kt * 32;
        const uint32_t sb = sbase + buf * GT_STAGE;
        #pragma unroll
        for (int i = 0; i < 2; i++) {
            const int ch = tid + i * 256;            // 0..511
            const int r = ch >> 2, c16 = ch & 3;
            const uint32_t off = (uint32_t)(r * GSTRIDE + c16 * 8) * 2;
            cp16(sb + off,            A  + (size_t)(bm + r) * K + k0 + c16 * 8);
            cp16(sb + GT_A + off,     Wh + (size_t)(bn + r) * K + k0 + c16 * 8);
            cp16(sb + 2*GT_A + off,   Wl + (size_t)(bn + r) * K + k0 + c16 * 8);
        }
        cp_commit();
    };

    float acc[4][4][4] = {};
    issue(0, 0);
    issue(1, 1);

    const int sub = lane & 7;
    const uint32_t a_off = ((uint32_t)((8 * ((lane >> 3) & 1) + sub) * GSTRIDE
                                       + (lane >> 4) * 8)) * 2;
    const uint32_t b_off = ((uint32_t)((8 * (lane >> 4) + sub) * GSTRIDE
                                       + ((lane >> 3) & 1) * 8)) * 2;

    const int NT = K / 32;
    for (int kt = 0; kt < NT; kt++) {
        if (kt < NT - 1) cp_wait<1>(); else cp_wait<0>();
        __syncthreads();

        const uint32_t stb = sbase + (kt & 1) * GT_STAGE;

        #pragma unroll
        for (int kh = 0; kh < 32; kh += 16) {
            const uint32_t Aaddr = stb + a_off + (uint32_t)(wm * GSTRIDE + kh) * 2;
            const uint32_t Baddr = stb + GT_A + b_off + (uint32_t)(wn * GSTRIDE + kh) * 2;
            uint32_t af[4][4], bh[2][4], bl[2][4];
            #pragma unroll
            for (int mi = 0; mi < 4; mi++)
                ldsm4(af[mi], Aaddr + (uint32_t)(mi * 16 * GSTRIDE) * 2);
            ldsm4(bh[0], Baddr);
            ldsm4(bh[1], Baddr + (uint32_t)(16 * GSTRIDE) * 2);
            #pragma unroll
            for (int mi = 0; mi < 4; mi++)
                #pragma unroll
                for (int ni = 0; ni < 4; ni++)
                    mma16816h(acc[mi][ni], af[mi], bh[ni >> 1] + (ni & 1) * 2);
            ldsm4(bl[0], Baddr + GT_A);
            ldsm4(bl[1], Baddr + GT_A + (uint32_t)(16 * GSTRIDE) * 2);
            #pragma unroll
            for (int mi = 0; mi < 4; mi++)
                #pragma unroll
                for (int ni = 0; ni < 4; ni++)
                    mma16816h(acc[mi][ni], af[mi], bl[ni >> 1] + (ni & 1) * 2);
        }
        __syncthreads();
        if (kt + 2 < NT) issue(kt + 2, kt & 1);
    }

    // epilogue
    #pragma unroll
    for (int ni = 0; ni < 4; ni++) {
        const int n0 = bn + wn + ni * 8 + 2 * tg;
        const float b0 = bias[n0], b1 = bias[n0 + 1];
        #pragma unroll
        for (int mi = 0; mi < 4; mi++) {
            #pragma unroll
            for (int h = 0; h < 2; h++) {
                const int row = bm + wm + mi * 16 + g + h * 8;
                float vx = acc[mi][ni][2*h+0] + b0;
                float vy = acc[mi][ni][2*h+1] + b1;
                if (MODE == 1) {
                    *(float2*)(outf + (size_t)row * H_ + n0) = make_float2(vx, vy);
                } else {
                    vx *= scale; vy *= scale;
                    const int b  = row >> 11;
                    const int s  = row & 2047;
                    const int hd = n0 >> 7;
                    const int dd = n0 & 127;
                    size_t idx = ((size_t)(b * NH + hd) * S_ + s) * HD + dd;
                    if (z == 0) {
                        *(__half2*)(oq + idx) = __floats2half2_rn(vx, vy);
                    } else {
                        __half* outhi = (z == 1) ? oh1 : oh2;
                        __half* outlo = (z == 1) ? ol1 : ol2;
                        __half hx, hy, lx, ly;
                        split1h(vx, hx, lx); split1h(vy, hy, ly);
                        *(__half2*)(outhi + idx) = __halves2half2(hx, hy);
                        *(__half2*)(outlo + idx) = __halves2half2(lx, ly);
                    }
                }
            }
        }
    }
}

// ---------------------------------------------------------------------------
// Flash attention v5: all fp16 2-term. Q single fp16 in regs; K fp16 hi/lo;
// QK^T = Qh*Kh + Qh*Kl. P single fp16; V fp16 hi/lo; PV = P*Vh + P*Vl.
// ctx out single fp16.
// ---------------------------------------------------------------------------
#define FV_K(st) ((st)*17408)
#define FV_V(st) (34816 + (st)*17408)
#define FV_SMEM_BYTES (69632*2)

__global__ __launch_bounds__(256) void flash_attn_v5(
    const __half* __restrict__ Qh,
    const __half* __restrict__ Khi, const __half* __restrict__ Klo,
    const __half* __restrict__ Vhi, const __half* __restrict__ Vlo,
    __half* __restrict__ Ch)
{
    __half* sm = (__half*)sm_raw;
    const int tid = threadIdx.x, lane = tid & 31, w = tid >> 5;
    const int g = lane >> 2, tg = lane & 3;
    const int bh = blockIdx.y, b = bh >> 4, head = bh & 15;
    const int q0 = (NQ - 1 - (int)blockIdx.x) * 128;
    const size_t base = (size_t)bh * S_ * HD;
    const uint32_t sb = smem_u32(sm);
    const int nt = q0 / 64 + 2;

    const int sub   = lane & 7;
    const int halfb = (lane >> 3) & 1;
    const int grpb  = lane >> 4;

    auto issueKV = [&](int kt, int st) {
        const int k0 = kt * 64;
        const uint32_t kb = sb + FV_K(st) * 2;
        const uint32_t vb = sb + FV_V(st) * 2;
        #pragma unroll
        for (int p = 0; p < 4; p++) {
            const int ch = tid + p * 256;
            const int r = ch >> 4, c8 = (ch & 15) * 8;
            const uint32_t off = (uint32_t)(r * 136 + c8) * 2;
            const size_t go = base + (size_t)(k0 + r) * HD + c8;
            cp16(kb + off,          Khi + go);
            cp16(kb + 17408 + off,  Klo + go);
            cp16(vb + off,          Vhi + go);
            cp16(vb + 17408 + off,  Vlo + go);
        }
        cp_commit();
    };

    issueKV(0, 0);

    // Q fragments (single fp16) -> registers
    uint32_t qf[8][4];
    {
        const size_t r0g = base + (size_t)(q0 + w * 16 + g) * HD;
        #pragma unroll
        for (int kk = 0; kk < 8; kk++) {
            const int c = kk * 16 + 2 * tg;
            qf[kk][0] = *(const uint32_t*)(Qh + r0g + c);
            qf[kk][1] = *(const uint32_t*)(Qh + r0g + 8 * HD + c);
            qf[kk][2] = *(const uint32_t*)(Qh + r0g + c + 8);
            qf[kk][3] = *(const uint32_t*)(Qh + r0g + 8 * HD + c + 8);
        }
    }

    float oacc[16][4] = {};
    float m0 = -1e30f, m1 = -1e30f, l0 = 0.f, l1 = 0.f;
    const int r0 = q0 + w * 16 + g;

    const uint32_t kfragoff = (uint32_t)((8 * grpb + sub) * 136 + halfb * 8) * 2;
    const uint32_t vfragoff = (uint32_t)((8 * halfb + sub) * 136 + 8 * grpb) * 2;

    for (int kt = 0; kt < nt; kt++) {
        const int st = kt & 1;
        __syncthreads();
        if (kt + 1 < nt) { issueKV(kt + 1, st ^ 1); cp_wait<1>(); }
        else             { cp_wait<0>(); }
        __syncthreads();

        // ---- S = Q K^T (fp16 2-term) ----
        float sacc[8][4];
        #pragma unroll
        for (int j = 0; j < 8; j++)
            sacc[j][0] = sacc[j][1] = sacc[j][2] = sacc[j][3] = 0.f;
        const uint32_t kbase = sb + FV_K(st) * 2 + kfragoff;
        #pragma unroll
        for (int kk = 0; kk < 8; kk++) {
            #pragma unroll
            for (int jp = 0; jp < 4; jp++) {
                uint32_t kh4[4], kl4[4];
                const uint32_t ka = kbase + (uint32_t)(16 * jp * 136 + kk * 16) * 2;
                ldsm4(kh4, ka);
                ldsm4(kl4, ka + 17408);
                mma16816h(sacc[2*jp],   qf[kk], kh4);
                mma16816h(sacc[2*jp+1], qf[kk], kh4 + 2);
                mma16816h(sacc[2*jp],   qf[kk], kl4);
                mma16816h(sacc[2*jp+1], qf[kk], kl4 + 2);
            }
        }

        // ---- causal mask ----
        const int k0 = kt * 64;
        if (k0 + 63 > r0) {
            #pragma unroll
            for (int j = 0; j < 8; j++) {
                const int c = k0 + j * 8 + 2 * tg;
                if (c     > r0)     sacc[j][0] = -1e30f;
                if (c + 1 > r0)     sacc[j][1] = -1e30f;
                if (c     > r0 + 8) sacc[j][2] = -1e30f;
                if (c + 1 > r0 + 8) sacc[j][3] = -1e30f;
            }
        }

        // ---- online softmax (P single fp16) ----
        float rx0 = -1e30f, rx1 = -1e30f;
        #pragma unroll
        for (int j = 0; j < 8; j++) {
            rx0 = fmaxf(rx0, fmaxf(sacc[j][0], sacc[j][1]));
            rx1 = fmaxf(rx1, fmaxf(sacc[j][2], sacc[j][3]));
        }
        rx0 = fmaxf(rx0, __shfl_xor_sync(0xffffffffu, rx0, 1));
        rx0 = fmaxf(rx0, __shfl_xor_sync(0xffffffffu, rx0, 2));
        rx1 = fmaxf(rx1, __shfl_xor_sync(0xffffffffu, rx1, 1));
        rx1 = fmaxf(rx1, __shfl_xor_sync(0xffffffffu, rx1, 2));
        const float mn0 = fmaxf(m0, rx0), mn1 = fmaxf(m1, rx1);
        const float c0 = __expf(m0 - mn0), c1 = __expf(m1 - mn1);

        uint32_t ph0[8], ph1[8];
        float sum0 = 0.f, sum1 = 0.f;
        #pragma unroll
        for (int j = 0; j < 8; j++) {
            float p00 = __expf(sacc[j][0] - mn0);
            float p01 = __expf(sacc[j][1] - mn0);
            float p10 = __expf(sacc[j][2] - mn1);
            float p11 = __expf(sacc[j][3] - mn1);
            sum0 += p00 + p01;  sum1 += p10 + p11;
            ph0[j] = packh(p00, p01);
            ph1[j] = packh(p10, p11);
        }
        sum0 += __shfl_xor_sync(0xffffffffu, sum0, 1);
        sum0 += __shfl_xor_sync(0xffffffffu, sum0, 2);
        sum1 += __shfl_xor_sync(0xffffffffu, sum1, 1);
        sum1 += __shfl_xor_sync(0xffffffffu, sum1, 2);
        l0 = l0 * c0 + sum0;  m0 = mn0;
        l1 = l1 * c1 + sum1;  m1 = mn1;
        #pragma unroll
        for (int jd = 0; jd < 16; jd++) {
            oacc[jd][0] *= c0; oacc[jd][1] *= c0;
            oacc[jd][2] *= c1; oacc[jd][3] *= c1;
        }

        // ---- O += P V (fp16, 2 terms) ----
        const uint32_t vbase = sb + FV_V(st) * 2 + vfragoff;
        #pragma unroll
        for (int kk2 = 0; kk2 < 4; kk2++) {
            uint32_t a_h[4] = { ph0[2*kk2], ph1[2*kk2], ph0[2*kk2+1], ph1[2*kk2+1] };
            #pragma unroll
            for (int jdp = 0; jdp < 8; jdp++) {
                uint32_t vh4[4], vl4[4];
                const uint32_t va = vbase + (uint32_t)(16 * kk2 * 136 + 16 * jdp) * 2;
                ldsm4t(vh4, va);
                ldsm4t(vl4, va + 17408);
                mma16816h(oacc[2*jdp],   a_h, vh4);
                mma16816h(oacc[2*jdp+1], a_h, vh4 + 2);
                mma16816h(oacc[2*jdp],   a_h, vl4);
                mma16816h(oacc[2*jdp+1], a_h, vl4 + 2);
            }
        }
    }

    // ---- epilogue: single fp16 ctx ----
    const float i0 = 1.f / l0, i1 = 1.f / l1;
    #pragma unroll
    for (int jd = 0; jd < 16; jd++) {
        const int d = jd * 8 + 2 * tg;
        const size_t idx0 = ((size_t)b * S_ + r0)     * H_ + head * HD + d;
        const size_t idx1 = ((size_t)b * S_ + r0 + 8) * H_ + head * HD + d;
        *(__half2*)(Ch + idx0) = __floats2half2_rn(oacc[jd][0] * i0, oacc[jd][1] * i0);
        *(__half2*)(Ch + idx1) = __floats2half2_rn(oacc[jd][2] * i1, oacc[jd][3] * i1);
    }
}

// ---------------------------------------------------------------------------
extern "C" void kernel_launch(void* const* d_in, const int* in_sizes, int n_in,
                              void* d_out, int out_size)
{
    const float* x  = (const float*)d_in[0];
    const float* wq = (const float*)d_in[1];
    const float* bq = (const float*)d_in[2];
    const float* wk = (const float*)d_in[3];
    const float* bk = (const float*)d_in[4];
    const float* wv = (const float*)d_in[5];
    const float* bv = (const float*)d_in[6];
    const float* wo = (const float*)d_in[7];
    const float* bo = (const float*)d_in[8];
    float* out = (float*)d_out;

    __half *xh, *wh, *wl, *qh, *khi, *klo, *vhi, *vlo, *ch;
    cudaGetSymbolAddress((void**)&xh,  g_xh);
    cudaGetSymbolAddress((void**)&wh,  g_wh);
    cudaGetSymbolAddress((void**)&wl,  g_wl);
    cudaGetSymbolAddress((void**)&qh,  g_qh);
    cudaGetSymbolAddress((void**)&khi, g_khi);
    cudaGetSymbolAddress((void**)&klo, g_klo);
    cudaGetSymbolAddress((void**)&vhi, g_vhi);
    cudaGetSymbolAddress((void**)&vlo, g_vlo);
    cudaGetSymbolAddress((void**)&ch,  g_ch);

    static bool attr_set = false;
    if (!attr_set) {
        cudaFuncSetAttribute(gemm_fp16x2<0>, cudaFuncAttributeMaxDynamicSharedMemorySize, GEMM_SMEM_BYTES);
        cudaFuncSetAttribute(gemm_fp16x2<1>, cudaFuncAttributeMaxDynamicSharedMemorySize, GEMM_SMEM_BYTES);
        cudaFuncSetAttribute(flash_attn_v5, cudaFuncAttributeMaxDynamicSharedMemorySize, FV_SMEM_BYTES);
        attr_set = true;
    }

    const float qscale = 0.08838834764831845f;   // 1/sqrt(128)

    split_all<<<dim3(256, 5), 256>>>(x, wq, wk, wv, wo, xh, wh, wl,
                                     M_*H_/4, H_*H_/4);

    dim3 gqkv(H_/128, M_/128, 3);   // (16, 32, 3)
    gemm_fp16x2<0><<<gqkv, 256, GEMM_SMEM_BYTES>>>(
        xh, wh, wl, bq, bk, bv, qscale, nullptr,
        qh, khi, klo, vhi, vlo);

    dim3 gf(NQ, B_*NH);   // (16, 32)
    flash_attn_v5<<<gf, 256, FV_SMEM_BYTES>>>(qh, khi, klo, vhi, vlo, ch);

    dim3 gg(H_/128, M_/128);
    gemm_fp16x2<1><<<gg, 256, GEMM_SMEM_BYTES>>>(
        ch, wh + 3*(size_t)H_*H_, wl + 3*(size_t)H_*H_,
        bo, bo, bo, 1.f, out,
        nullptr, nullptr, nullptr, nullptr, nullptr);
}

// round 16
// speedup vs baseline: 2.2052x; 1.3954x over previous
#include <cuda_runtime.h>
#include <cuda_bf16.h>
#include <cuda_fp16.h>
#include <cstdint>

#define B_  2
#define S_  2048
#define H_  2048
#define NH  16
#define HD  128
#define M_  (B_*S_)
#define NQ  (S_/128)

extern __shared__ __align__(16) unsigned char sm_raw[];

// ---------------------------------------------------------------------------
// Scratch
// ---------------------------------------------------------------------------
__device__ __half g_xh [(size_t)M_*H_];    // x, single fp16
__device__ __half g_wh [4][(size_t)H_*H_]; // weights single fp16
__device__ __half g_qh [(size_t)M_*H_];    // Q single fp16, pre-scaled [b,h,s,d]
__device__ __half g_khi[(size_t)M_*H_];    // K fp16 hi/lo [b,h,s,d]
__device__ __half g_klo[(size_t)M_*H_];
__device__ __half g_vhi[(size_t)M_*H_];    // V fp16 hi/lo [b,h,s,d]
__device__ __half g_vlo[(size_t)M_*H_];
__device__ __half g_ch [(size_t)M_*H_];    // ctx [b,s,h], single fp16

// ---------------------------------------------------------------------------
__device__ __forceinline__ void split1h(float v, __half& h, __half& l) {
    h = __float2half_rn(v);
    l = __float2half_rn(v - __half2float(h));
}

// Fused converter: y=0 -> x (n4x); y=1..4 -> weights (n4w each); all single fp16
__global__ void conv_all(const float* __restrict__ x,
                         const float* __restrict__ w0, const float* __restrict__ w1,
                         const float* __restrict__ w2, const float* __restrict__ w3,
                         __half* __restrict__ xh, __half* __restrict__ wh,
                         int n4x, int n4w)
{
    const int which = blockIdx.y;
    const float* in;
    __half* dst;
    int n4;
    if (which == 0) { in = x; dst = xh; n4 = n4x; }
    else {
        const float* src[4] = {w0, w1, w2, w3};
        in = src[which - 1];
        dst = wh + (size_t)(which - 1) * H_ * H_;
        n4 = n4w;
    }
    int i = blockIdx.x * blockDim.x + threadIdx.x;
    int stride = gridDim.x * blockDim.x;
    for (; i < n4; i += stride) {
        float4 v = ((const float4*)in)[i];
        ((__half2*)dst)[2*i+0] = __floats2half2_rn(v.x, v.y);
        ((__half2*)dst)[2*i+1] = __floats2half2_rn(v.z, v.w);
    }
}

// ---------------------------------------------------------------------------
// PTX helpers
// ---------------------------------------------------------------------------
__device__ __forceinline__ uint32_t smem_u32(const void* p) {
    uint32_t a;
    asm("{ .reg .u64 t; cvta.to.shared.u64 t, %1; cvt.u32.u64 %0, t; }" : "=r"(a) : "l"(p));
    return a;
}
__device__ __forceinline__ void cp16(uint32_t s, const void* g) {
    asm volatile("cp.async.cg.shared.global [%0], [%1], 16;\n" :: "r"(s), "l"(g));
}
__device__ __forceinline__ void cp_commit() { asm volatile("cp.async.commit_group;\n"); }
template<int N> __device__ __forceinline__ void cp_wait() {
    asm volatile("cp.async.wait_group %0;\n" :: "n"(N));
}
__device__ __forceinline__ void mma16816h(float* d, const uint32_t* a, const uint32_t* b) {
    asm volatile("mma.sync.aligned.m16n8k16.row.col.f32.f16.f16.f32 "
                 "{%0,%1,%2,%3}, {%4,%5,%6,%7}, {%8,%9}, {%0,%1,%2,%3};\n"
                 : "+f"(d[0]), "+f"(d[1]), "+f"(d[2]), "+f"(d[3])
                 : "r"(a[0]), "r"(a[1]), "r"(a[2]), "r"(a[3]), "r"(b[0]), "r"(b[1]));
}
__device__ __forceinline__ void ldsm4(uint32_t* r, uint32_t a) {
    asm volatile("ldmatrix.sync.aligned.m8n8.x4.shared.b16 {%0,%1,%2,%3}, [%4];"
                 : "=r"(r[0]), "=r"(r[1]), "=r"(r[2]), "=r"(r[3]) : "r"(a));
}
__device__ __forceinline__ void ldsm4t(uint32_t* r, uint32_t a) {
    asm volatile("ldmatrix.sync.aligned.m8n8.x4.trans.shared.b16 {%0,%1,%2,%3}, [%4];"
                 : "=r"(r[0]), "=r"(r[1]), "=r"(r[2]), "=r"(r[3]) : "r"(a));
}
__device__ __forceinline__ uint32_t packh(float a, float b) {
    __half2 h = __floats2half2_rn(a, b);
    return *(uint32_t*)&h;
}

// ---------------------------------------------------------------------------
// fp16 GEMM (NT, 1 term): C = A * W^T + bias; A, W single fp16.
// BM=BN=128, BK=32, 256 threads, warp tile 64x32, ldmatrix, 2 CTA/SM.
// MODE 0: QKV fused via blockIdx.z; z=0 -> single fp16 out (Q, *scale);
//         z=1,2 -> fp16 hi/lo out (K, V).
// MODE 1: fp32 out [M,N].
// smem/stage: A 10240 + W 10240 = 20480 B; double-buffered = 40960 B.
// ---------------------------------------------------------------------------
#define GSTRIDE 40
#define GT_A 10240
#define GT_STAGE 20480
#define GEMM_SMEM_BYTES (2*GT_STAGE)

template<int MODE>
__global__ __launch_bounds__(256, 2) void gemm_fp16(
    const __half* __restrict__ A,
    const __half* __restrict__ Wh_base,
    const float* __restrict__ bias0, const float* __restrict__ bias1,
    const float* __restrict__ bias2, float scale0,
    float* __restrict__ outf,
    __half* __restrict__ oq,
    __half* __restrict__ oh1, __half* __restrict__ ol1,
    __half* __restrict__ oh2, __half* __restrict__ ol2)
{
    const int K = H_;
    const int tid  = threadIdx.x;
    const int lane = tid & 31, warp = tid >> 5;
    const int g = lane >> 2, tg = lane & 3;
    const int wm = (warp >> 2) * 64, wn = (warp & 3) * 32;
    const int bm = blockIdx.y * 128, bn = blockIdx.x * 128;
    const int z = (MODE == 0) ? blockIdx.z : 0;

    const __half* Wh = Wh_base + (size_t)z * H_ * H_;
    const float* bias = (z == 0) ? bias0 : (z == 1) ? bias1 : bias2;
    const float scale = (MODE == 0 && z == 0) ? scale0 : 1.f;

    const uint32_t sbase = smem_u32(sm_raw);

    auto issue = [&](int kt, int buf) {
        const int k0 = kt * 32;
        const uint32_t sb = sbase + buf * GT_STAGE;
        #pragma unroll
        for (int i = 0; i < 2; i++) {
            const int ch = tid + i * 256;            // 0..511
            const int r = ch >> 2, c16 = ch & 3;
            const uint32_t off = (uint32_t)(r * GSTRIDE + c16 * 8) * 2;
            cp16(sb + off,         A  + (size_t)(bm + r) * K + k0 + c16 * 8);
            cp16(sb + GT_A + off,  Wh + (size_t)(bn + r) * K + k0 + c16 * 8);
        }
        cp_commit();
    };

    float acc[4][4][4] = {};
    issue(0, 0);
    issue(1, 1);

    const int sub = lane & 7;
    const uint32_t a_off = ((uint32_t)((8 * ((lane >> 3) & 1) + sub) * GSTRIDE
                                       + (lane >> 4) * 8)) * 2;
    const uint32_t b_off = ((uint32_t)((8 * (lane >> 4) + sub) * GSTRIDE
                                       + ((lane >> 3) & 1) * 8)) * 2;

    const int NT = K / 32;
    for (int kt = 0; kt < NT; kt++) {
        if (kt < NT - 1) cp_wait<1>(); else cp_wait<0>();
        __syncthreads();

        const uint32_t stb = sbase + (kt & 1) * GT_STAGE;

        #pragma unroll
        for (int kh = 0; kh < 32; kh += 16) {
            const uint32_t Aaddr = stb + a_off + (uint32_t)(wm * GSTRIDE + kh) * 2;
            const uint32_t Baddr = stb + GT_A + b_off + (uint32_t)(wn * GSTRIDE + kh) * 2;
            uint32_t af[4][4], bh[2][4];
            #pragma unroll
            for (int mi = 0; mi < 4; mi++)
                ldsm4(af[mi], Aaddr + (uint32_t)(mi * 16 * GSTRIDE) * 2);
            ldsm4(bh[0], Baddr);
            ldsm4(bh[1], Baddr + (uint32_t)(16 * GSTRIDE) * 2);
            #pragma unroll
            for (int mi = 0; mi < 4; mi++)
                #pragma unroll
                for (int ni = 0; ni < 4; ni++)
                    mma16816h(acc[mi][ni], af[mi], bh[ni >> 1] + (ni & 1) * 2);
        }
        __syncthreads();
        if (kt + 2 < NT) issue(kt + 2, kt & 1);
    }

    // epilogue
    #pragma unroll
    for (int ni = 0; ni < 4; ni++) {
        const int n0 = bn + wn + ni * 8 + 2 * tg;
        const float b0 = bias[n0], b1 = bias[n0 + 1];
        #pragma unroll
        for (int mi = 0; mi < 4; mi++) {
            #pragma unroll
            for (int h = 0; h < 2; h++) {
                const int row = bm + wm + mi * 16 + g + h * 8;
                float vx = acc[mi][ni][2*h+0] + b0;
                float vy = acc[mi][ni][2*h+1] + b1;
                if (MODE == 1) {
                    *(float2*)(outf + (size_t)row * H_ + n0) = make_float2(vx, vy);
                } else {
                    vx *= scale; vy *= scale;
                    const int b  = row >> 11;
                    const int s  = row & 2047;
                    const int hd = n0 >> 7;
                    const int dd = n0 & 127;
                    size_t idx = ((size_t)(b * NH + hd) * S_ + s) * HD + dd;
                    if (z == 0) {
                        *(__half2*)(oq + idx) = __floats2half2_rn(vx, vy);
                    } else {
                        __half* outhi = (z == 1) ? oh1 : oh2;
                        __half* outlo = (z == 1) ? ol1 : ol2;
                        __half hx, hy, lx, ly;
                        split1h(vx, hx, lx); split1h(vy, hy, ly);
                        *(__half2*)(outhi + idx) = __halves2half2(hx, hy);
                        *(__half2*)(outlo + idx) = __halves2half2(lx, ly);
                    }
                }
            }
        }
    }
}

// ---------------------------------------------------------------------------
// Flash attention v5 (unchanged from R15): Q single fp16 in regs; K fp16 hi/lo;
// QK^T 2-term; P single fp16; V fp16 hi/lo; PV 2-term; ctx single fp16.
// ---------------------------------------------------------------------------
#define FV_K(st) ((st)*17408)
#define FV_V(st) (34816 + (st)*17408)
#define FV_SMEM_BYTES (69632*2)

__global__ __launch_bounds__(256) void flash_attn_v5(
    const __half* __restrict__ Qh,
    const __half* __restrict__ Khi, const __half* __restrict__ Klo,
    const __half* __restrict__ Vhi, const __half* __restrict__ Vlo,
    __half* __restrict__ Ch)
{
    __half* sm = (__half*)sm_raw;
    const int tid = threadIdx.x, lane = tid & 31, w = tid >> 5;
    const int g = lane >> 2, tg = lane & 3;
    const int bh = blockIdx.y, b = bh >> 4, head = bh & 15;
    const int q0 = (NQ - 1 - (int)blockIdx.x) * 128;
    const size_t base = (size_t)bh * S_ * HD;
    const uint32_t sb = smem_u32(sm);
    const int nt = q0 / 64 + 2;

    const int sub   = lane & 7;
    const int halfb = (lane >> 3) & 1;
    const int grpb  = lane >> 4;

    auto issueKV = [&](int kt, int st) {
        const int k0 = kt * 64;
        const uint32_t kb = sb + FV_K(st) * 2;
        const uint32_t vb = sb + FV_V(st) * 2;
        #pragma unroll
        for (int p = 0; p < 4; p++) {
            const int ch = tid + p * 256;
            const int r = ch >> 4, c8 = (ch & 15) * 8;
            const uint32_t off = (uint32_t)(r * 136 + c8) * 2;
            const size_t go = base + (size_t)(k0 + r) * HD + c8;
            cp16(kb + off,          Khi + go);
            cp16(kb + 17408 + off,  Klo + go);
            cp16(vb + off,          Vhi + go);
            cp16(vb + 17408 + off,  Vlo + go);
        }
        cp_commit();
    };

    issueKV(0, 0);

    uint32_t qf[8][4];
    {
        const size_t r0g = base + (size_t)(q0 + w * 16 + g) * HD;
        #pragma unroll
        for (int kk = 0; kk < 8; kk++) {
            const int c = kk * 16 + 2 * tg;
            qf[kk][0] = *(const uint32_t*)(Qh + r0g + c);
            qf[kk][1] = *(const uint32_t*)(Qh + r0g + 8 * HD + c);
            qf[kk][2] = *(const uint32_t*)(Qh + r0g + c + 8);
            qf[kk][3] = *(const uint32_t*)(Qh + r0g + 8 * HD + c + 8);
        }
    }

    float oacc[16][4] = {};
    float m0 = -1e30f, m1 = -1e30f, l0 = 0.f, l1 = 0.f;
    const int r0 = q0 + w * 16 + g;

    const uint32_t kfragoff = (uint32_t)((8 * grpb + sub) * 136 + halfb * 8) * 2;
    const uint32_t vfragoff = (uint32_t)((8 * halfb + sub) * 136 + 8 * grpb) * 2;

    for (int kt = 0; kt < nt; kt++) {
        const int st = kt & 1;
        __syncthreads();
        if (kt + 1 < nt) { issueKV(kt + 1, st ^ 1); cp_wait<1>(); }
        else             { cp_wait<0>(); }
        __syncthreads();

        float sacc[8][4];
        #pragma unroll
        for (int j = 0; j < 8; j++)
            sacc[j][0] = sacc[j][1] = sacc[j][2] = sacc[j][3] = 0.f;
        const uint32_t kbase = sb + FV_K(st) * 2 + kfragoff;
        #pragma unroll
        for (int kk = 0; kk < 8; kk++) {
            #pragma unroll
            for (int jp = 0; jp < 4; jp++) {
                uint32_t kh4[4], kl4[4];
                const uint32_t ka = kbase + (uint32_t)(16 * jp * 136 + kk * 16) * 2;
                ldsm4(kh4, ka);
                ldsm4(kl4, ka + 17408);
                mma16816h(sacc[2*jp],   qf[kk], kh4);
                mma16816h(sacc[2*jp+1], qf[kk], kh4 + 2);
                mma16816h(sacc[2*jp],   qf[kk], kl4);
                mma16816h(sacc[2*jp+1], qf[kk], kl4 + 2);
            }
        }

        const int k0 = kt * 64;
        if (k0 + 63 > r0) {
            #pragma unroll
            for (int j = 0; j < 8; j++) {
                const int c = k0 + j * 8 + 2 * tg;
                if (c     > r0)     sacc[j][0] = -1e30f;
                if (c + 1 > r0)     sacc[j][1] = -1e30f;
                if (c     > r0 + 8) sacc[j][2] = -1e30f;
                if (c + 1 > r0 + 8) sacc[j][3] = -1e30f;
            }
        }

        float rx0 = -1e30f, rx1 = -1e30f;
        #pragma unroll
        for (int j = 0; j < 8; j++) {
            rx0 = fmaxf(rx0, fmaxf(sacc[j][0], sacc[j][1]));
            rx1 = fmaxf(rx1, fmaxf(sacc[j][2], sacc[j][3]));
        }
        rx0 = fmaxf(rx0, __shfl_xor_sync(0xffffffffu, rx0, 1));
        rx0 = fmaxf(rx0, __shfl_xor_sync(0xffffffffu, rx0, 2));
        rx1 = fmaxf(rx1, __shfl_xor_sync(0xffffffffu, rx1, 1));
        rx1 = fmaxf(rx1, __shfl_xor_sync(0xffffffffu, rx1, 2));
        const float mn0 = fmaxf(m0, rx0), mn1 = fmaxf(m1, rx1);
        const float c0 = __expf(m0 - mn0), c1 = __expf(m1 - mn1);

        uint32_t ph0[8], ph1[8];
        float sum0 = 0.f, sum1 = 0.f;
        #pragma unroll
        for (int j = 0; j < 8; j++) {
            float p00 = __expf(sacc[j][0] - mn0);
            float p01 = __expf(sacc[j][1] - mn0);
            float p10 = __expf(sacc[j][2] - mn1);
            float p11 = __expf(sacc[j][3] - mn1);
            sum0 += p00 + p01;  sum1 += p10 + p11;
            ph0[j] = packh(p00, p01);
            ph1[j] = packh(p10, p11);
        }
        sum0 += __shfl_xor_sync(0xffffffffu, sum0, 1);
        sum0 += __shfl_xor_sync(0xffffffffu, sum0, 2);
        sum1 += __shfl_xor_sync(0xffffffffu, sum1, 1);
        sum1 += __shfl_xor_sync(0xffffffffu, sum1, 2);
        l0 = l0 * c0 + sum0;  m0 = mn0;
        l1 = l1 * c1 + sum1;  m1 = mn1;
        #pragma unroll
        for (int jd = 0; jd < 16; jd++) {
            oacc[jd][0] *= c0; oacc[jd][1] *= c0;
            oacc[jd][2] *= c1; oacc[jd][3] *= c1;
        }

        const uint32_t vbase = sb + FV_V(st) * 2 + vfragoff;
        #pragma unroll
        for (int kk2 = 0; kk2 < 4; kk2++) {
            uint32_t a_h[4] = { ph0[2*kk2], ph1[2*kk2], ph0[2*kk2+1], ph1[2*kk2+1] };
            #pragma unroll
            for (int jdp = 0; jdp < 8; jdp++) {
                uint32_t vh4[4], vl4[4];
                const uint32_t va = vbase + (uint32_t)(16 * kk2 * 136 + 16 * jdp) * 2;
                ldsm4t(vh4, va);
                ldsm4t(vl4, va + 17408);
                mma16816h(oacc[2*jdp],   a_h, vh4);
                mma16816h(oacc[2*jdp+1], a_h, vh4 + 2);
                mma16816h(oacc[2*jdp],   a_h, vl4);
                mma16816h(oacc[2*jdp+1], a_h, vl4 + 2);
            }
        }
    }

    const float i0 = 1.f / l0, i1 = 1.f / l1;
    #pragma unroll
    for (int jd = 0; jd < 16; jd++) {
        const int d = jd * 8 + 2 * tg;
        const size_t idx0 = ((size_t)b * S_ + r0)     * H_ + head * HD + d;
        const size_t idx1 = ((size_t)b * S_ + r0 + 8) * H_ + head * HD + d;
        *(__half2*)(Ch + idx0) = __floats2half2_rn(oacc[jd][0] * i0, oacc[jd][1] * i0);
        *(__half2*)(Ch + idx1) = __floats2half2_rn(oacc[jd][2] * i1, oacc[jd][3] * i1);
    }
}

// ---------------------------------------------------------------------------
extern "C" void kernel_launch(void* const* d_in, const int* in_sizes, int n_in,
                              void* d_out, int out_size)
{
    const float* x  = (const float*)d_in[0];
    const float* wq = (const float*)d_in[1];
    const float* bq = (const float*)d_in[2];
    const float* wk = (const float*)d_in[3];
    const float* bk = (const float*)d_in[4];
    const float* wv = (const float*)d_in[5];
    const float* bv = (const float*)d_in[6];
    const float* wo = (const float*)d_in[7];
    const float* bo = (const float*)d_in[8];
    float* out = (float*)d_out;

    __half *xh, *wh, *qh, *khi, *klo, *vhi, *vlo, *ch;
    cudaGetSymbolAddress((void**)&xh,  g_xh);
    cudaGetSymbolAddress((void**)&wh,  g_wh);
    cudaGetSymbolAddress((void**)&qh,  g_qh);
    cudaGetSymbolAddress((void**)&khi, g_khi);
    cudaGetSymbolAddress((void**)&klo, g_klo);
    cudaGetSymbolAddress((void**)&vhi, g_vhi);
    cudaGetSymbolAddress((void**)&vlo, g_vlo);
    cudaGetSymbolAddress((void**)&ch,  g_ch);

    static bool attr_set = false;
    if (!attr_set) {
        cudaFuncSetAttribute(gemm_fp16<0>, cudaFuncAttributeMaxDynamicSharedMemorySize, GEMM_SMEM_BYTES);
        cudaFuncSetAttribute(gemm_fp16<1>, cudaFuncAttributeMaxDynamicSharedMemorySize, GEMM_SMEM_BYTES);
        cudaFuncSetAttribute(flash_attn_v5, cudaFuncAttributeMaxDynamicSharedMemorySize, FV_SMEM_BYTES);
        attr_set = true;
    }

    const float qscale = 0.08838834764831845f;   // 1/sqrt(128)

    conv_all<<<dim3(256, 5), 256>>>(x, wq, wk, wv, wo, xh, wh, M_*H_/4, H_*H_/4);

    dim3 gqkv(H_/128, M_/128, 3);   // (16, 32, 3)
    gemm_fp16<0><<<gqkv, 256, GEMM_SMEM_BYTES>>>(
        xh, wh, bq, bk, bv, qscale, nullptr,
        qh, khi, klo, vhi, vlo);

    dim3 gf(NQ, B_*NH);   // (16, 32)
    flash_attn_v5<<<gf, 256, FV_SMEM_BYTES>>>(qh, khi, klo, vhi, vlo, ch);

    dim3 gg(H_/128, M_/128);
    gemm_fp16<1><<<gg, 256, GEMM_SMEM_BYTES>>>(
        ch, wh + 3*(size_t)H_*H_, bo, bo, bo, 1.f, out,
        nullptr, nullptr, nullptr, nullptr, nullptr);
}

// round 17
// speedup vs baseline: 2.6412x; 1.1977x over previous
#include <cuda_runtime.h>
#include <cuda_bf16.h>
#include <cuda_fp16.h>
#include <cstdint>

#define B_  2
#define S_  2048
#define H_  2048
#define NH  16
#define HD  128
#define M_  (B_*S_)
#define NQ  (S_/128)

extern __shared__ __align__(16) unsigned char sm_raw[];

// ---------------------------------------------------------------------------
// Scratch (all single fp16 now)
// ---------------------------------------------------------------------------
__device__ __half g_xh[(size_t)M_*H_];    // x
__device__ __half g_wh[4][(size_t)H_*H_]; // weights
__device__ __half g_qh[(size_t)M_*H_];    // Q pre-scaled [b,h,s,d]
__device__ __half g_kh[(size_t)M_*H_];    // K [b,h,s,d]
__device__ __half g_vh[(size_t)M_*H_];    // V [b,h,s,d]
__device__ __half g_ch[(size_t)M_*H_];    // ctx [b,s,h]

// ---------------------------------------------------------------------------
// Fused converter: y=0 -> x (n4x); y=1..4 -> weights (n4w each)
__global__ void conv_all(const float* __restrict__ x,
                         const float* __restrict__ w0, const float* __restrict__ w1,
                         const float* __restrict__ w2, const float* __restrict__ w3,
                         __half* __restrict__ xh, __half* __restrict__ wh,
                         int n4x, int n4w)
{
    const int which = blockIdx.y;
    const float* in;
    __half* dst;
    int n4;
    if (which == 0) { in = x; dst = xh; n4 = n4x; }
    else {
        const float* src[4] = {w0, w1, w2, w3};
        in = src[which - 1];
        dst = wh + (size_t)(which - 1) * H_ * H_;
        n4 = n4w;
    }
    int i = blockIdx.x * blockDim.x + threadIdx.x;
    int stride = gridDim.x * blockDim.x;
    for (; i < n4; i += stride) {
        float4 v = ((const float4*)in)[i];
        ((__half2*)dst)[2*i+0] = __floats2half2_rn(v.x, v.y);
        ((__half2*)dst)[2*i+1] = __floats2half2_rn(v.z, v.w);
    }
}

// ---------------------------------------------------------------------------
// PTX helpers
// ---------------------------------------------------------------------------
__device__ __forceinline__ uint32_t smem_u32(const void* p) {
    uint32_t a;
    asm("{ .reg .u64 t; cvta.to.shared.u64 t, %1; cvt.u32.u64 %0, t; }" : "=r"(a) : "l"(p));
    return a;
}
__device__ __forceinline__ void cp16(uint32_t s, const void* g) {
    asm volatile("cp.async.cg.shared.global [%0], [%1], 16;\n" :: "r"(s), "l"(g));
}
__device__ __forceinline__ void cp_commit() { asm volatile("cp.async.commit_group;\n"); }
template<int N> __device__ __forceinline__ void cp_wait() {
    asm volatile("cp.async.wait_group %0;\n" :: "n"(N));
}
__device__ __forceinline__ void mma16816h(float* d, const uint32_t* a, const uint32_t* b) {
    asm volatile("mma.sync.aligned.m16n8k16.row.col.f32.f16.f16.f32 "
                 "{%0,%1,%2,%3}, {%4,%5,%6,%7}, {%8,%9}, {%0,%1,%2,%3};\n"
                 : "+f"(d[0]), "+f"(d[1]), "+f"(d[2]), "+f"(d[3])
                 : "r"(a[0]), "r"(a[1]), "r"(a[2]), "r"(a[3]), "r"(b[0]), "r"(b[1]));
}
__device__ __forceinline__ void ldsm4(uint32_t* r, uint32_t a) {
    asm volatile("ldmatrix.sync.aligned.m8n8.x4.shared.b16 {%0,%1,%2,%3}, [%4];"
                 : "=r"(r[0]), "=r"(r[1]), "=r"(r[2]), "=r"(r[3]) : "r"(a));
}
__device__ __forceinline__ void ldsm4t(uint32_t* r, uint32_t a) {
    asm volatile("ldmatrix.sync.aligned.m8n8.x4.trans.shared.b16 {%0,%1,%2,%3}, [%4];"
                 : "=r"(r[0]), "=r"(r[1]), "=r"(r[2]), "=r"(r[3]) : "r"(a));
}
__device__ __forceinline__ uint32_t packh(float a, float b) {
    __half2 h = __floats2half2_rn(a, b);
    return *(uint32_t*)&h;
}

// ---------------------------------------------------------------------------
// fp16 GEMM (NT, 1 term): C = A * W^T + bias, 3-stage cp.async pipeline.
// BM=BN=128, BK=32, 256 threads, warp tile 64x32, ldmatrix, 2 CTA/SM.
// MODE 0: QKV fused via blockIdx.z -> single fp16 out (Q *scale).
// MODE 1: fp32 out [M,N].
// smem/stage: A 10240 + W 10240 = 20480 B; 3 stages = 61440 B.
// ---------------------------------------------------------------------------
#define GSTRIDE 40
#define GT_A 10240
#define GT_STAGE 20480
#define GEMM_SMEM_BYTES (3*GT_STAGE)

template<int MODE>
__global__ __launch_bounds__(256, 2) void gemm_fp16(
    const __half* __restrict__ A,
    const __half* __restrict__ Wh_base,
    const float* __restrict__ bias0, const float* __restrict__ bias1,
    const float* __restrict__ bias2, float scale0,
    float* __restrict__ outf,
    __half* __restrict__ o0, __half* __restrict__ o1, __half* __restrict__ o2)
{
    const int K = H_;
    const int tid  = threadIdx.x;
    const int lane = tid & 31, warp = tid >> 5;
    const int g = lane >> 2, tg = lane & 3;
    const int wm = (warp >> 2) * 64, wn = (warp & 3) * 32;
    const int bm = blockIdx.y * 128, bn = blockIdx.x * 128;
    const int z = (MODE == 0) ? blockIdx.z : 0;

    const __half* Wh = Wh_base + (size_t)z * H_ * H_;
    const float* bias = (z == 0) ? bias0 : (z == 1) ? bias1 : bias2;
    const float scale = (MODE == 0 && z == 0) ? scale0 : 1.f;
    __half* oh = (z == 0) ? o0 : (z == 1) ? o1 : o2;

    const uint32_t sbase = smem_u32(sm_raw);

    auto issue = [&](int kt, int buf) {
        const int k0 = kt * 32;
        const uint32_t sb = sbase + buf * GT_STAGE;
        #pragma unroll
        for (int i = 0; i < 2; i++) {
            const int ch = tid + i * 256;            // 0..511
            const int r = ch >> 2, c16 = ch & 3;
            const uint32_t off = (uint32_t)(r * GSTRIDE + c16 * 8) * 2;
            cp16(sb + off,         A  + (size_t)(bm + r) * K + k0 + c16 * 8);
            cp16(sb + GT_A + off,  Wh + (size_t)(bn + r) * K + k0 + c16 * 8);
        }
        cp_commit();
    };

    float acc[4][4][4] = {};
    issue(0, 0);
    issue(1, 1);
    issue(2, 2);

    const int sub = lane & 7;
    const uint32_t a_off = ((uint32_t)((8 * ((lane >> 3) & 1) + sub) * GSTRIDE
                                       + (lane >> 4) * 8)) * 2;
    const uint32_t b_off = ((uint32_t)((8 * (lane >> 4) + sub) * GSTRIDE
                                       + ((lane >> 3) & 1) * 8)) * 2;

    const int NT = K / 32;   // 64
    int buf = 0;
    for (int kt = 0; kt < NT; kt++) {
        if (kt < NT - 2)      cp_wait<2>();
        else if (kt == NT - 2) cp_wait<1>();
        else                   cp_wait<0>();
        __syncthreads();

        const uint32_t stb = sbase + buf * GT_STAGE;

        #pragma unroll
        for (int kh = 0; kh < 32; kh += 16) {
            const uint32_t Aaddr = stb + a_off + (uint32_t)(wm * GSTRIDE + kh) * 2;
            const uint32_t Baddr = stb + GT_A + b_off + (uint32_t)(wn * GSTRIDE + kh) * 2;
            uint32_t af[4][4], bh[2][4];
            #pragma unroll
            for (int mi = 0; mi < 4; mi++)
                ldsm4(af[mi], Aaddr + (uint32_t)(mi * 16 * GSTRIDE) * 2);
            ldsm4(bh[0], Baddr);
            ldsm4(bh[1], Baddr + (uint32_t)(16 * GSTRIDE) * 2);
            #pragma unroll
            for (int mi = 0; mi < 4; mi++)
                #pragma unroll
                for (int ni = 0; ni < 4; ni++)
                    mma16816h(acc[mi][ni], af[mi], bh[ni >> 1] + (ni & 1) * 2);
        }
        __syncthreads();
        if (kt + 3 < NT) issue(kt + 3, buf);
        buf = (buf == 2) ? 0 : buf + 1;
    }

    // epilogue
    #pragma unroll
    for (int ni = 0; ni < 4; ni++) {
        const int n0 = bn + wn + ni * 8 + 2 * tg;
        const float b0 = bias[n0], b1 = bias[n0 + 1];
        #pragma unroll
        for (int mi = 0; mi < 4; mi++) {
            #pragma unroll
            for (int h = 0; h < 2; h++) {
                const int row = bm + wm + mi * 16 + g + h * 8;
                float vx = acc[mi][ni][2*h+0] + b0;
                float vy = acc[mi][ni][2*h+1] + b1;
                if (MODE == 1) {
                    *(float2*)(outf + (size_t)row * H_ + n0) = make_float2(vx, vy);
                } else {
                    vx *= scale; vy *= scale;
                    const int b  = row >> 11;
                    const int s  = row & 2047;
                    const int hd = n0 >> 7;
                    const int dd = n0 & 127;
                    size_t idx = ((size_t)(b * NH + hd) * S_ + s) * HD + dd;
                    *(__half2*)(oh + idx) = __floats2half2_rn(vx, vy);
                }
            }
        }
    }
}

// ---------------------------------------------------------------------------
// Flash attention v6: all single fp16, 1-term QK and PV.
// 256 threads, BR=128, BC=64, Q frags in regs, K ldmatrix, V ldmatrix.trans.
// smem (fp16 elems): K st: st*8704; V st: 17408 + st*8704.  69632 B total.
// ---------------------------------------------------------------------------
#define FV_K(st) ((st)*8704)
#define FV_V(st) (17408 + (st)*8704)
#define FV_SMEM_BYTES (34816*2)

__global__ __launch_bounds__(256) void flash_attn_v6(
    const __half* __restrict__ Qh, const __half* __restrict__ Kh,
    const __half* __restrict__ Vh, __half* __restrict__ Ch)
{
    __half* sm = (__half*)sm_raw;
    const int tid = threadIdx.x, lane = tid & 31, w = tid >> 5;
    const int g = lane >> 2, tg = lane & 3;
    const int bh = blockIdx.y, b = bh >> 4, head = bh & 15;
    const int q0 = (NQ - 1 - (int)blockIdx.x) * 128;
    const size_t base = (size_t)bh * S_ * HD;
    const uint32_t sb = smem_u32(sm);
    const int nt = q0 / 64 + 2;

    const int sub   = lane & 7;
    const int halfb = (lane >> 3) & 1;
    const int grpb  = lane >> 4;

    auto issueKV = [&](int kt, int st) {
        const int k0 = kt * 64;
        const uint32_t kb = sb + FV_K(st) * 2;
        const uint32_t vb = sb + FV_V(st) * 2;
        #pragma unroll
        for (int p = 0; p < 4; p++) {
            const int ch = tid + p * 256;            // 0..1023
            const int r = ch >> 4, c8 = (ch & 15) * 8;
            const uint32_t off = (uint32_t)(r * 136 + c8) * 2;
            const size_t go = base + (size_t)(k0 + r) * HD + c8;
            cp16(kb + off, Kh + go);
            cp16(vb + off, Vh + go);
        }
        cp_commit();
    };

    issueKV(0, 0);

    uint32_t qf[8][4];
    {
        const size_t r0g = base + (size_t)(q0 + w * 16 + g) * HD;
        #pragma unroll
        for (int kk = 0; kk < 8; kk++) {
            const int c = kk * 16 + 2 * tg;
            qf[kk][0] = *(const uint32_t*)(Qh + r0g + c);
            qf[kk][1] = *(const uint32_t*)(Qh + r0g + 8 * HD + c);
            qf[kk][2] = *(const uint32_t*)(Qh + r0g + c + 8);
            qf[kk][3] = *(const uint32_t*)(Qh + r0g + 8 * HD + c + 8);
        }
    }

    float oacc[16][4] = {};
    float m0 = -1e30f, m1 = -1e30f, l0 = 0.f, l1 = 0.f;
    const int r0 = q0 + w * 16 + g;

    const uint32_t kfragoff = (uint32_t)((8 * grpb + sub) * 136 + halfb * 8) * 2;
    const uint32_t vfragoff = (uint32_t)((8 * halfb + sub) * 136 + 8 * grpb) * 2;

    for (int kt = 0; kt < nt; kt++) {
        const int st = kt & 1;
        __syncthreads();
        if (kt + 1 < nt) { issueKV(kt + 1, st ^ 1); cp_wait<1>(); }
        else             { cp_wait<0>(); }
        __syncthreads();

        // ---- S = Q K^T (fp16, 1 term) ----
        float sacc[8][4];
        #pragma unroll
        for (int j = 0; j < 8; j++)
            sacc[j][0] = sacc[j][1] = sacc[j][2] = sacc[j][3] = 0.f;
        const uint32_t kbase = sb + FV_K(st) * 2 + kfragoff;
        #pragma unroll
        for (int kk = 0; kk < 8; kk++) {
            #pragma unroll
            for (int jp = 0; jp < 4; jp++) {
                uint32_t kh4[4];
                const uint32_t ka = kbase + (uint32_t)(16 * jp * 136 + kk * 16) * 2;
                ldsm4(kh4, ka);
                mma16816h(sacc[2*jp],   qf[kk], kh4);
                mma16816h(sacc[2*jp+1], qf[kk], kh4 + 2);
            }
        }

        // ---- causal mask ----
        const int k0 = kt * 64;
        if (k0 + 63 > r0) {
            #pragma unroll
            for (int j = 0; j < 8; j++) {
                const int c = k0 + j * 8 + 2 * tg;
                if (c     > r0)     sacc[j][0] = -1e30f;
                if (c + 1 > r0)     sacc[j][1] = -1e30f;
                if (c     > r0 + 8) sacc[j][2] = -1e30f;
                if (c + 1 > r0 + 8) sacc[j][3] = -1e30f;
            }
        }

        // ---- online softmax (P single fp16) ----
        float rx0 = -1e30f, rx1 = -1e30f;
        #pragma unroll
        for (int j = 0; j < 8; j++) {
            rx0 = fmaxf(rx0, fmaxf(sacc[j][0], sacc[j][1]));
            rx1 = fmaxf(rx1, fmaxf(sacc[j][2], sacc[j][3]));
        }
        rx0 = fmaxf(rx0, __shfl_xor_sync(0xffffffffu, rx0, 1));
        rx0 = fmaxf(rx0, __shfl_xor_sync(0xffffffffu, rx0, 2));
        rx1 = fmaxf(rx1, __shfl_xor_sync(0xffffffffu, rx1, 1));
        rx1 = fmaxf(rx1, __shfl_xor_sync(0xffffffffu, rx1, 2));
        const float mn0 = fmaxf(m0, rx0), mn1 = fmaxf(m1, rx1);
        const float c0 = __expf(m0 - mn0), c1 = __expf(m1 - mn1);

        uint32_t ph0[8], ph1[8];
        float sum0 = 0.f, sum1 = 0.f;
        #pragma unroll
        for (int j = 0; j < 8; j++) {
            float p00 = __expf(sacc[j][0] - mn0);
            float p01 = __expf(sacc[j][1] - mn0);
            float p10 = __expf(sacc[j][2] - mn1);
            float p11 = __expf(sacc[j][3] - mn1);
            sum0 += p00 + p01;  sum1 += p10 + p11;
            ph0[j] = packh(p00, p01);
            ph1[j] = packh(p10, p11);
        }
        sum0 += __shfl_xor_sync(0xffffffffu, sum0, 1);
        sum0 += __shfl_xor_sync(0xffffffffu, sum0, 2);
        sum1 += __shfl_xor_sync(0xffffffffu, sum1, 1);
        sum1 += __shfl_xor_sync(0xffffffffu, sum1, 2);
        l0 = l0 * c0 + sum0;  m0 = mn0;
        l1 = l1 * c1 + sum1;  m1 = mn1;
        #pragma unroll
        for (int jd = 0; jd < 16; jd++) {
            oacc[jd][0] *= c0; oacc[jd][1] *= c0;
            oacc[jd][2] *= c1; oacc[jd][3] *= c1;
        }

        // ---- O += P V (fp16, 1 term) ----
        const uint32_t vbase = sb + FV_V(st) * 2 + vfragoff;
        #pragma unroll
        for (int kk2 = 0; kk2 < 4; kk2++) {
            uint32_t a_h[4] = { ph0[2*kk2], ph1[2*kk2], ph0[2*kk2+1], ph1[2*kk2+1] };
            #pragma unroll
            for (int jdp = 0; jdp < 8; jdp++) {
                uint32_t vh4[4];
                const uint32_t va = vbase + (uint32_t)(16 * kk2 * 136 + 16 * jdp) * 2;
                ldsm4t(vh4, va);
                mma16816h(oacc[2*jdp],   a_h, vh4);
                mma16816h(oacc[2*jdp+1], a_h, vh4 + 2);
            }
        }
    }

    // ---- epilogue: single fp16 ctx ----
    const float i0 = 1.f / l0, i1 = 1.f / l1;
    #pragma unroll
    for (int jd = 0; jd < 16; jd++) {
        const int d = jd * 8 + 2 * tg;
        const size_t idx0 = ((size_t)b * S_ + r0)     * H_ + head * HD + d;
        const size_t idx1 = ((size_t)b * S_ + r0 + 8) * H_ + head * HD + d;
        *(__half2*)(Ch + idx0) = __floats2half2_rn(oacc[jd][0] * i0, oacc[jd][1] * i0);
        *(__half2*)(Ch + idx1) = __floats2half2_rn(oacc[jd][2] * i1, oacc[jd][3] * i1);
    }
}

// ---------------------------------------------------------------------------
extern "C" void kernel_launch(void* const* d_in, const int* in_sizes, int n_in,
                              void* d_out, int out_size)
{
    const float* x  = (const float*)d_in[0];
    const float* wq = (const float*)d_in[1];
    const float* bq = (const float*)d_in[2];
    const float* wk = (const float*)d_in[3];
    const float* bk = (const float*)d_in[4];
    const float* wv = (const float*)d_in[5];
    const float* bv = (const float*)d_in[6];
    const float* wo = (const float*)d_in[7];
    const float* bo = (const float*)d_in[8];
    float* out = (float*)d_out;

    __half *xh, *wh, *qh, *kh, *vh, *ch;
    cudaGetSymbolAddress((void**)&xh, g_xh);
    cudaGetSymbolAddress((void**)&wh, g_wh);
    cudaGetSymbolAddress((void**)&qh, g_qh);
    cudaGetSymbolAddress((void**)&kh, g_kh);
    cudaGetSymbolAddress((void**)&vh, g_vh);
    cudaGetSymbolAddress((void**)&ch, g_ch);

    static bool attr_set = false;
    if (!attr_set) {
        cudaFuncSetAttribute(gemm_fp16<0>, cudaFuncAttributeMaxDynamicSharedMemorySize, GEMM_SMEM_BYTES);
        cudaFuncSetAttribute(gemm_fp16<1>, cudaFuncAttributeMaxDynamicSharedMemorySize, GEMM_SMEM_BYTES);
        cudaFuncSetAttribute(flash_attn_v6, cudaFuncAttributeMaxDynamicSharedMemorySize, FV_SMEM_BYTES);
        attr_set = true;
    }

    const float qscale = 0.08838834764831845f;   // 1/sqrt(128)

    conv_all<<<dim3(256, 5), 256>>>(x, wq, wk, wv, wo, xh, wh, M_*H_/4, H_*H_/4);

    dim3 gqkv(H_/128, M_/128, 3);   // (16, 32, 3)
    gemm_fp16<0><<<gqkv, 256, GEMM_SMEM_BYTES>>>(
        xh, wh, bq, bk, bv, qscale, nullptr, qh, kh, vh);

    dim3 gf(NQ, B_*NH);   // (16, 32)
    flash_attn_v6<<<gf, 256, FV_SMEM_BYTES>>>(qh, kh, vh, ch);

    dim3 gg(H_/128, M_/128);
    gemm_fp16<1><<<gg, 256, GEMM_SMEM_BYTES>>>(
        ch, wh + 3*(size_t)H_*H_, bo, bo, bo, 1.f, out,
        nullptr, nullptr, nullptr);
}